// round 1
// baseline (speedup 1.0000x reference)
#include <cuda_runtime.h>
#include <math.h>

// Problem constants
#define NN_   4096      // nodes
#define EE_   131072    // edges
#define IN_   500
#define HH_   500
#define OUT_  100
#define CC_   15451
#define NHEAD 4
#define HD_   125

// ---------------- scratch (static device globals; no allocation) -------------
__device__ float g_deg[NN_];
__device__ float g_agg[NN_ * HH_];        // used for IN_(=500) and HH_(=500)
__device__ float g_mean[NN_ * HH_];
__device__ float g_h1[NN_ * HH_];
__device__ float g_qkv[NN_ * 3 * HH_];
__device__ float g_scores[(size_t)NHEAD * NN_ * NN_];   // 268 MB
__device__ float g_attno[NN_ * HH_];
__device__ float g_h2[NN_ * HH_];

// ---------------- simple elementwise kernels --------------------------------
__global__ void zero_kernel(float* p, int n) {
    int i = blockIdx.x * blockDim.x + threadIdx.x;
    int stride = gridDim.x * blockDim.x;
    for (; i < n; i += stride) p[i] = 0.f;
}

__global__ void deg_kernel(const int* __restrict__ ei) {
    int e = blockIdx.x * blockDim.x + threadIdx.x;
    if (e < EE_) atomicAdd(&g_deg[ei[EE_ + e]], 1.0f);
}

__global__ void scatter_add_kernel(const float* __restrict__ feat,
                                   float* __restrict__ agg,
                                   const int* __restrict__ ei, int F) {
    long long idx = (long long)blockIdx.x * blockDim.x + threadIdx.x;
    long long total = (long long)EE_ * F;
    if (idx >= total) return;
    int e = (int)(idx / F);
    int f = (int)(idx % F);
    int s = ei[e];          // src
    int d = ei[EE_ + e];    // dst
    atomicAdd(&agg[(size_t)d * F + f], feat[(size_t)s * F + f]);
}

__global__ void mean_kernel(const float* __restrict__ agg,
                            float* __restrict__ mean, int F) {
    int idx = blockIdx.x * blockDim.x + threadIdx.x;
    if (idx >= NN_ * F) return;
    int row = idx / F;
    mean[idx] = agg[idx] / fmaxf(g_deg[row], 1.0f);
}

// ---------------- tiled GEMMs ------------------------------------------------
// C[M,N] = alpha * (A1 @ B1^T [+ A2 @ B2^T]) + bias, optional relu
// A row-major [M,K] stride lda; B row-major [N,K] stride ldb.
#define TM 128
#define TN 128
#define BK 16
#define SPAD 4

__global__ __launch_bounds__(256)
void gemm_nt_kernel(const float* __restrict__ A1, int lda1,
                    const float* __restrict__ B1, int ldb1,
                    const float* __restrict__ A2, int lda2,
                    const float* __restrict__ B2, int ldb2,
                    const float* __restrict__ bias,
                    float* __restrict__ C, int ldc,
                    int M, int N, int K, float alpha, int do_relu) {
    __shared__ float As[BK][TM + SPAD];
    __shared__ float Bs[BK][TN + SPAD];
    int t  = threadIdx.x;
    int tx = t & 15, ty = t >> 4;
    int bm = blockIdx.y * TM, bn = blockIdx.x * TN;

    float acc[8][8];
    #pragma unroll
    for (int i = 0; i < 8; i++)
        #pragma unroll
        for (int j = 0; j < 8; j++) acc[i][j] = 0.f;

    int npairs = (A2 != nullptr) ? 2 : 1;
    for (int p = 0; p < npairs; ++p) {
        const float* A = p ? A2 : A1; int lda = p ? lda2 : lda1;
        const float* B = p ? B2 : B1; int ldb = p ? ldb2 : ldb1;
        for (int k0 = 0; k0 < K; k0 += BK) {
            #pragma unroll
            for (int i = 0; i < 8; ++i) {
                int l   = t + i * 256;
                int kk  = l & 15;
                int row = l >> 4;
                int gk  = k0 + kk;
                int gm  = bm + row;
                int gn  = bn + row;
                As[kk][row] = (gm < M && gk < K) ? A[(size_t)gm * lda + gk] : 0.f;
                Bs[kk][row] = (gn < N && gk < K) ? B[(size_t)gn * ldb + gk] : 0.f;
            }
            __syncthreads();
            #pragma unroll
            for (int kk = 0; kk < BK; ++kk) {
                float a[8], b[8];
                #pragma unroll
                for (int i = 0; i < 8; i++) a[i] = As[kk][ty * 8 + i];
                #pragma unroll
                for (int j = 0; j < 8; j++) b[j] = Bs[kk][tx * 8 + j];
                #pragma unroll
                for (int i = 0; i < 8; i++)
                    #pragma unroll
                    for (int j = 0; j < 8; j++)
                        acc[i][j] = fmaf(a[i], b[j], acc[i][j]);
            }
            __syncthreads();
        }
    }

    #pragma unroll
    for (int i = 0; i < 8; i++) {
        int gm = bm + ty * 8 + i;
        if (gm >= M) continue;
        #pragma unroll
        for (int j = 0; j < 8; j++) {
            int gn = bn + tx * 8 + j;
            if (gn >= N) continue;
            float v = alpha * acc[i][j];
            if (bias) v += bias[gn];
            if (do_relu) v = fmaxf(v, 0.f);
            C[(size_t)gm * ldc + gn] = v;
        }
    }
}

// C[M,N] = A[M,K] @ B[K,N]; A stride lda, B stride ldb (both row-major)
__global__ __launch_bounds__(256)
void gemm_nn_kernel(const float* __restrict__ A, int lda,
                    const float* __restrict__ B, int ldb,
                    float* __restrict__ C, int ldc,
                    int M, int N, int K) {
    __shared__ float As[BK][TM + SPAD];
    __shared__ float Bs[BK][TN + SPAD];
    int t  = threadIdx.x;
    int tx = t & 15, ty = t >> 4;
    int bm = blockIdx.y * TM, bn = blockIdx.x * TN;

    float acc[8][8];
    #pragma unroll
    for (int i = 0; i < 8; i++)
        #pragma unroll
        for (int j = 0; j < 8; j++) acc[i][j] = 0.f;

    for (int k0 = 0; k0 < K; k0 += BK) {
        #pragma unroll
        for (int i = 0; i < 8; ++i) {
            int l   = t + i * 256;
            // A: kk fastest (coalesced along K)
            int kkA  = l & 15;
            int rowA = l >> 4;
            int gk   = k0 + kkA;
            int gm   = bm + rowA;
            As[kkA][rowA] = (gm < M && gk < K) ? A[(size_t)gm * lda + gk] : 0.f;
            // B: col fastest (coalesced along N)
            int colB = l & 127;
            int kkB  = l >> 7;
            int gkb  = k0 + kkB;
            int gn   = bn + colB;
            Bs[kkB][colB] = (gn < N && gkb < K) ? B[(size_t)gkb * ldb + gn] : 0.f;
        }
        __syncthreads();
        #pragma unroll
        for (int kk = 0; kk < BK; ++kk) {
            float a[8], b[8];
            #pragma unroll
            for (int i = 0; i < 8; i++) a[i] = As[kk][ty * 8 + i];
            #pragma unroll
            for (int j = 0; j < 8; j++) b[j] = Bs[kk][tx * 8 + j];
            #pragma unroll
            for (int i = 0; i < 8; i++)
                #pragma unroll
                for (int j = 0; j < 8; j++)
                    acc[i][j] = fmaf(a[i], b[j], acc[i][j]);
        }
        __syncthreads();
    }

    #pragma unroll
    for (int i = 0; i < 8; i++) {
        int gm = bm + ty * 8 + i;
        if (gm >= M) continue;
        #pragma unroll
        for (int j = 0; j < 8; j++) {
            int gn = bn + tx * 8 + j;
            if (gn >= N) continue;
            C[(size_t)gm * ldc + gn] = acc[i][j];
        }
    }
}

// ---------------- softmax over rows of length ncol ---------------------------
__global__ __launch_bounds__(256)
void softmax_kernel(float* __restrict__ S, int ncol) {
    size_t row = blockIdx.x;
    float* p = S + row * (size_t)ncol;
    int t = threadIdx.x;
    __shared__ float red[32];

    // max
    float m = -1e30f;
    for (int i = t; i < ncol; i += 256) m = fmaxf(m, p[i]);
    #pragma unroll
    for (int o = 16; o > 0; o >>= 1) m = fmaxf(m, __shfl_xor_sync(0xffffffffu, m, o));
    if ((t & 31) == 0) red[t >> 5] = m;
    __syncthreads();
    if (t < 32) {
        float v = (t < 8) ? red[t] : -1e30f;
        #pragma unroll
        for (int o = 4; o > 0; o >>= 1) v = fmaxf(v, __shfl_xor_sync(0xffffffffu, v, o));
        red[t] = v;
    }
    __syncthreads();
    m = red[0];
    __syncthreads();

    // sum of exp
    float s = 0.f;
    for (int i = t; i < ncol; i += 256) {
        float e = expf(p[i] - m);
        p[i] = e;
        s += e;
    }
    #pragma unroll
    for (int o = 16; o > 0; o >>= 1) s += __shfl_xor_sync(0xffffffffu, s, o);
    if ((t & 31) == 0) red[t >> 5] = s;
    __syncthreads();
    if (t < 32) {
        float v = (t < 8) ? red[t] : 0.f;
        #pragma unroll
        for (int o = 4; o > 0; o >>= 1) v += __shfl_xor_sync(0xffffffffu, v, o);
        red[t] = v;
    }
    __syncthreads();
    s = red[0];

    float inv = 1.0f / s;
    for (int i = t; i < ncol; i += 256) p[i] *= inv;
}

// ---------------- launch -----------------------------------------------------
extern "C" void kernel_launch(void* const* d_in, const int* in_sizes, int n_in,
                              void* d_out, int out_size) {
    const float* x        = (const float*)d_in[0];
    const int*   ei       = (const int*)d_in[1];
    const float* W1_self  = (const float*)d_in[2];
    const float* W1_neigh = (const float*)d_in[3];
    const float* b1       = (const float*)d_in[4];
    const float* W_in     = (const float*)d_in[5];
    const float* b_in     = (const float*)d_in[6];
    const float* W_out    = (const float*)d_in[7];
    const float* b_out    = (const float*)d_in[8];
    const float* W2_self  = (const float*)d_in[9];
    const float* W2_neigh = (const float*)d_in[10];
    const float* b2       = (const float*)d_in[11];
    const float* Wc       = (const float*)d_in[12];
    const float* bc       = (const float*)d_in[13];

    float* out_x      = (float*)d_out;                       // [N, OUT]
    float* out_logits = (float*)d_out + (size_t)NN_ * OUT_;  // [N, C]

    float *deg, *agg, *mean, *h1, *qkv, *scores, *attno, *h2;
    cudaGetSymbolAddress((void**)&deg,    g_deg);
    cudaGetSymbolAddress((void**)&agg,    g_agg);
    cudaGetSymbolAddress((void**)&mean,   g_mean);
    cudaGetSymbolAddress((void**)&h1,     g_h1);
    cudaGetSymbolAddress((void**)&qkv,    g_qkv);
    cudaGetSymbolAddress((void**)&scores, g_scores);
    cudaGetSymbolAddress((void**)&attno,  g_attno);
    cudaGetSymbolAddress((void**)&h2,     g_h2);

    const float scale = 1.0f / sqrtf((float)HD_);

    // ---- SAGE 1 ----
    zero_kernel<<<1024, 256>>>(deg, NN_);
    zero_kernel<<<4096, 256>>>(agg, NN_ * IN_);
    deg_kernel<<<(EE_ + 255) / 256, 256>>>(ei);
    {
        long long total = (long long)EE_ * IN_;
        scatter_add_kernel<<<(unsigned)((total + 255) / 256), 256>>>(x, agg, ei, IN_);
    }
    mean_kernel<<<(NN_ * IN_ + 255) / 256, 256>>>(agg, mean, IN_);

    {
        dim3 grid((HH_ + TN - 1) / TN, (NN_ + TM - 1) / TM);
        gemm_nt_kernel<<<grid, 256>>>(x, IN_, W1_self, IN_, mean, IN_, W1_neigh, IN_,
                                      b1, h1, HH_, NN_, HH_, IN_, 1.0f, 1);
    }

    // ---- MHA ----
    {
        dim3 grid((3 * HH_ + TN - 1) / TN, (NN_ + TM - 1) / TM);
        gemm_nt_kernel<<<grid, 256>>>(h1, HH_, W_in, HH_, nullptr, 0, nullptr, 0,
                                      b_in, qkv, 3 * HH_, NN_, 3 * HH_, HH_, 1.0f, 0);
    }
    for (int h = 0; h < NHEAD; ++h) {
        dim3 grid(NN_ / TN, NN_ / TM);
        gemm_nt_kernel<<<grid, 256>>>(qkv + h * HD_, 3 * HH_,
                                      qkv + HH_ + h * HD_, 3 * HH_,
                                      nullptr, 0, nullptr, 0, nullptr,
                                      scores + (size_t)h * NN_ * NN_, NN_,
                                      NN_, NN_, HD_, scale, 0);
    }
    softmax_kernel<<<NHEAD * NN_, 256>>>(scores, NN_);
    for (int h = 0; h < NHEAD; ++h) {
        dim3 grid((HD_ + TN - 1) / TN, NN_ / TM);
        gemm_nn_kernel<<<grid, 256>>>(scores + (size_t)h * NN_ * NN_, NN_,
                                      qkv + 2 * HH_ + h * HD_, 3 * HH_,
                                      attno + h * HD_, HH_,
                                      NN_, HD_, NN_);
    }
    {
        dim3 grid((HH_ + TN - 1) / TN, (NN_ + TM - 1) / TM);
        gemm_nt_kernel<<<grid, 256>>>(attno, HH_, W_out, HH_, nullptr, 0, nullptr, 0,
                                      b_out, h2, HH_, NN_, HH_, HH_, 1.0f, 1);
    }

    // ---- SAGE 2 ----
    zero_kernel<<<4096, 256>>>(agg, NN_ * HH_);
    {
        long long total = (long long)EE_ * HH_;
        scatter_add_kernel<<<(unsigned)((total + 255) / 256), 256>>>(h2, agg, ei, HH_);
    }
    mean_kernel<<<(NN_ * HH_ + 255) / 256, 256>>>(agg, mean, HH_);
    {
        dim3 grid((OUT_ + TN - 1) / TN, (NN_ + TM - 1) / TM);
        gemm_nt_kernel<<<grid, 256>>>(h2, HH_, W2_self, HH_, mean, HH_, W2_neigh, HH_,
                                      b2, out_x, OUT_, NN_, OUT_, HH_, 1.0f, 1);
    }

    // ---- classifier ----
    {
        dim3 grid((CC_ + TN - 1) / TN, (NN_ + TM - 1) / TM);
        gemm_nt_kernel<<<grid, 256>>>(out_x, OUT_, Wc, OUT_, nullptr, 0, nullptr, 0,
                                      bc, out_logits, CC_, NN_, CC_, OUT_, 1.0f, 0);
    }
}

// round 2
// speedup vs baseline: 1.6945x; 1.6945x over previous
#include <cuda_runtime.h>
#include <math.h>
#include <stdint.h>

#define NN_   4096
#define EE_   131072
#define IN_   500
#define HH_   500
#define OUT_  100
#define CC_   15451
#define NHEAD 4
#define HD_   125
#define KSPLIT 2

// ---------------- scratch ----------------------------------------------------
__device__ float g_deg[NN_];
__device__ float g_agg[NN_ * HH_];
__device__ float g_mean[NN_ * HH_];
__device__ float g_h1[NN_ * HH_];
__device__ float g_qkv[NN_ * 3 * HH_];
__device__ float g_scores[(size_t)NHEAD * NN_ * NN_];
__device__ float g_attno[NN_ * HH_];
__device__ float g_h2[NN_ * HH_];

// ---------------- helpers ----------------------------------------------------
__device__ __forceinline__ float4 ldg4(const float* p, int valid) {
    float4 v = make_float4(0.f, 0.f, 0.f, 0.f);
    if (valid >= 4 && ((((uintptr_t)p) & 15) == 0)) {
        v = *(const float4*)p;
    } else {
        if (valid > 0) v.x = __ldg(p);
        if (valid > 1) v.y = __ldg(p + 1);
        if (valid > 2) v.z = __ldg(p + 2);
        if (valid > 3) v.w = __ldg(p + 3);
    }
    return v;
}

// ---------------- elementwise ------------------------------------------------
__global__ void zero_kernel(float* p, int n) {
    int i = blockIdx.x * blockDim.x + threadIdx.x;
    int stride = gridDim.x * blockDim.x;
    for (; i < n; i += stride) p[i] = 0.f;
}

__global__ void deg_kernel(const int* __restrict__ ei) {
    int e = blockIdx.x * blockDim.x + threadIdx.x;
    if (e < EE_) atomicAdd(&g_deg[ei[EE_ + e]], 1.0f);
}

// one thread per (edge, 4-feature group)
__global__ void scatter_add4_kernel(const float* __restrict__ feat,
                                    float* __restrict__ agg,
                                    const int* __restrict__ ei, int F4, int F) {
    int idx = blockIdx.x * blockDim.x + threadIdx.x;
    int total = EE_ * F4;
    if (idx >= total) return;
    int e = idx / F4;
    int g = idx - e * F4;
    int s = __ldg(&ei[e]);
    int d = __ldg(&ei[EE_ + e]);
    float4 v = *((const float4*)(feat + (size_t)s * F) + g);
    float* o = agg + (size_t)d * F + g * 4;
    atomicAdd(o + 0, v.x);
    atomicAdd(o + 1, v.y);
    atomicAdd(o + 2, v.z);
    atomicAdd(o + 3, v.w);
}

__global__ void mean_kernel(const float* __restrict__ agg,
                            float* __restrict__ mean, int F) {
    int idx = blockIdx.x * blockDim.x + threadIdx.x;
    if (idx >= NN_ * F) return;
    int row = idx / F;
    mean[idx] = agg[idx] / fmaxf(g_deg[row], 1.0f);
}

// ---------------- GEMM NT: C = alpha*(A1@B1^T [+A2@B2^T]) + bias, opt relu ---
// A [M,K] row-major, B [N,K] row-major. Tiles 128x128x8, double-buffered.
// blockIdx.z indexes an extra batch dim with strides zsA/zsB/zsC (elements).
__global__ __launch_bounds__(256)
void gemm_nt_v2(const float* __restrict__ A1, int lda1,
                const float* __restrict__ B1, int ldb1,
                const float* __restrict__ A2, int lda2,
                const float* __restrict__ B2, int ldb2,
                const float* __restrict__ bias,
                float* __restrict__ C, int ldc,
                int M, int N, int K, float alpha, int relu,
                size_t zsA, size_t zsB, size_t zsC) {
    __shared__ float As[2][8][132];
    __shared__ float Bs[2][8][132];
    int t  = threadIdx.x;
    int tx = t & 15, ty = t >> 4;
    int bm = blockIdx.y * 128, bn = blockIdx.x * 128;
    int z  = blockIdx.z;

    float acc[8][8];
    #pragma unroll
    for (int i = 0; i < 8; i++)
        #pragma unroll
        for (int j = 0; j < 8; j++) acc[i][j] = 0.f;

    const int row = t >> 1;
    const int kq  = (t & 1) * 4;
    const bool am = (bm + row) < M;
    const bool bnok = (bn + row) < N;

    for (int p = 0; p < 2; ++p) {
        const float* A = p ? A2 : A1;
        if (A == nullptr) break;
        const float* B = p ? B2 : B1;
        int lda = p ? lda2 : lda1;
        int ldb = p ? ldb2 : ldb1;
        A += (size_t)z * zsA;
        B += (size_t)z * zsB;

        const float* ap = A + (size_t)(bm + row) * lda + kq;
        const float* bp = B + (size_t)(bn + row) * ldb + kq;

        __syncthreads();  // protect smem[0] from previous pair's readers
        {
            int avail = K - kq;
            float4 va = ldg4(ap, am ? avail : 0);
            float4 vb = ldg4(bp, bnok ? avail : 0);
            As[0][kq + 0][row] = va.x; As[0][kq + 1][row] = va.y;
            As[0][kq + 2][row] = va.z; As[0][kq + 3][row] = va.w;
            Bs[0][kq + 0][row] = vb.x; Bs[0][kq + 1][row] = vb.y;
            Bs[0][kq + 2][row] = vb.z; Bs[0][kq + 3][row] = vb.w;
        }
        __syncthreads();

        int buf = 0;
        for (int k0 = 0; k0 < K; k0 += 8) {
            int kn = k0 + 8;
            bool have = kn < K;
            float4 va, vb;
            if (have) {
                int avail = K - (kn + kq);
                va = ldg4(ap + kn, am ? avail : 0);
                vb = ldg4(bp + kn, bnok ? avail : 0);
            }
            #pragma unroll
            for (int kk = 0; kk < 8; ++kk) {
                float4 a0 = *(const float4*)&As[buf][kk][ty * 8];
                float4 a1 = *(const float4*)&As[buf][kk][ty * 8 + 4];
                float4 b0 = *(const float4*)&Bs[buf][kk][tx * 8];
                float4 b1 = *(const float4*)&Bs[buf][kk][tx * 8 + 4];
                float a[8] = {a0.x, a0.y, a0.z, a0.w, a1.x, a1.y, a1.z, a1.w};
                float b[8] = {b0.x, b0.y, b0.z, b0.w, b1.x, b1.y, b1.z, b1.w};
                #pragma unroll
                for (int i = 0; i < 8; i++)
                    #pragma unroll
                    for (int j = 0; j < 8; j++)
                        acc[i][j] = fmaf(a[i], b[j], acc[i][j]);
            }
            if (have) {
                int nb = buf ^ 1;
                As[nb][kq + 0][row] = va.x; As[nb][kq + 1][row] = va.y;
                As[nb][kq + 2][row] = va.z; As[nb][kq + 3][row] = va.w;
                Bs[nb][kq + 0][row] = vb.x; Bs[nb][kq + 1][row] = vb.y;
                Bs[nb][kq + 2][row] = vb.z; Bs[nb][kq + 3][row] = vb.w;
                __syncthreads();
                buf = nb;
            }
        }
    }

    C += (size_t)z * zsC;
    #pragma unroll
    for (int i = 0; i < 8; i++) {
        int gm = bm + ty * 8 + i;
        if (gm >= M) continue;
        #pragma unroll
        for (int j = 0; j < 8; j++) {
            int gn = bn + tx * 8 + j;
            if (gn >= N) continue;
            float v = alpha * acc[i][j];
            if (bias) v += bias[gn];
            if (relu) v = fmaxf(v, 0.f);
            C[(size_t)gm * ldc + gn] = v;
        }
    }
}

// ---------------- GEMM NN (PV): C += A@B, split-K + heads via grid.z ---------
// A [M,K] rm, B [K,N] rm. grid.z = head*KSPLIT + ks. K % (KSPLIT*8) == 0.
// Epilogue: atomicAdd into C (C must be pre-zeroed).
__global__ __launch_bounds__(256)
void gemm_nn_v2(const float* __restrict__ A, int lda,
                const float* __restrict__ B, int ldb,
                float* __restrict__ C, int ldc,
                int M, int N, int K,
                size_t zsA, size_t zsB, size_t zsC, int ksplit) {
    __shared__ float As[2][8][132];
    __shared__ float Bs[2][8][132];
    int t  = threadIdx.x;
    int tx = t & 15, ty = t >> 4;
    int bm = blockIdx.y * 128, bn = blockIdx.x * 128;
    int z  = blockIdx.z;
    int h  = z / ksplit;
    int ks = z - h * ksplit;
    int klen = K / ksplit;
    int kbeg = ks * klen;

    A += (size_t)h * zsA;
    B += (size_t)h * zsB;
    C += (size_t)h * zsC;

    float acc[8][8];
    #pragma unroll
    for (int i = 0; i < 8; i++)
        #pragma unroll
        for (int j = 0; j < 8; j++) acc[i][j] = 0.f;

    const int arow = t >> 1;
    const int akq  = (t & 1) * 4;
    const bool am  = (bm + arow) < M;
    const int bkk  = t >> 5;          // 0..7
    const int bcol = (t & 31) * 4;    // 0..124
    const int bn_valid = N - (bn + bcol);

    const float* ap = A + (size_t)(bm + arow) * lda + kbeg + akq;
    const float* bp = B + (size_t)(kbeg + bkk) * ldb + bn + bcol;

    {
        float4 va = ldg4(ap, am ? 4 : 0);              // klen % 8 == 0
        float4 vb = ldg4(bp, bn_valid);
        As[0][akq + 0][arow] = va.x; As[0][akq + 1][arow] = va.y;
        As[0][akq + 2][arow] = va.z; As[0][akq + 3][arow] = va.w;
        Bs[0][bkk][bcol + 0] = vb.x; Bs[0][bkk][bcol + 1] = vb.y;
        Bs[0][bkk][bcol + 2] = vb.z; Bs[0][bkk][bcol + 3] = vb.w;
    }
    __syncthreads();

    int buf = 0;
    for (int k0 = 0; k0 < klen; k0 += 8) {
        int kn = k0 + 8;
        bool have = kn < klen;
        float4 va, vb;
        if (have) {
            va = ldg4(ap + kn, am ? 4 : 0);
            vb = ldg4(bp + (size_t)kn * ldb, bn_valid);
        }
        #pragma unroll
        for (int kk = 0; kk < 8; ++kk) {
            float4 a0 = *(const float4*)&As[buf][kk][ty * 8];
            float4 a1 = *(const float4*)&As[buf][kk][ty * 8 + 4];
            float4 b0 = *(const float4*)&Bs[buf][kk][tx * 8];
            float4 b1 = *(const float4*)&Bs[buf][kk][tx * 8 + 4];
            float a[8] = {a0.x, a0.y, a0.z, a0.w, a1.x, a1.y, a1.z, a1.w};
            float b[8] = {b0.x, b0.y, b0.z, b0.w, b1.x, b1.y, b1.z, b1.w};
            #pragma unroll
            for (int i = 0; i < 8; i++)
                #pragma unroll
                for (int j = 0; j < 8; j++)
                    acc[i][j] = fmaf(a[i], b[j], acc[i][j]);
        }
        if (have) {
            int nb = buf ^ 1;
            As[nb][akq + 0][arow] = va.x; As[nb][akq + 1][arow] = va.y;
            As[nb][akq + 2][arow] = va.z; As[nb][akq + 3][arow] = va.w;
            Bs[nb][bkk][bcol + 0] = vb.x; Bs[nb][bkk][bcol + 1] = vb.y;
            Bs[nb][bkk][bcol + 2] = vb.z; Bs[nb][bkk][bcol + 3] = vb.w;
            __syncthreads();
            buf = nb;
        }
    }

    #pragma unroll
    for (int i = 0; i < 8; i++) {
        int gm = bm + ty * 8 + i;
        if (gm >= M) continue;
        #pragma unroll
        for (int j = 0; j < 8; j++) {
            int gn = bn + tx * 8 + j;
            if (gn >= N) continue;
            atomicAdd(&C[(size_t)gm * ldc + gn], acc[i][j]);
        }
    }
}

// ---------------- one-pass softmax (row length 4096) --------------------------
__global__ __launch_bounds__(256)
void softmax1_kernel(float* __restrict__ S) {
    size_t row = blockIdx.x;
    float4* p = (float4*)(S + row * (size_t)NN_);
    int t = threadIdx.x;
    __shared__ float red[8];

    float4 v[4];
    #pragma unroll
    for (int i = 0; i < 4; i++) v[i] = p[t + 256 * i];

    float m = -1e30f;
    #pragma unroll
    for (int i = 0; i < 4; i++) {
        m = fmaxf(m, fmaxf(fmaxf(v[i].x, v[i].y), fmaxf(v[i].z, v[i].w)));
    }
    #pragma unroll
    for (int o = 16; o > 0; o >>= 1) m = fmaxf(m, __shfl_xor_sync(0xffffffffu, m, o));
    if ((t & 31) == 0) red[t >> 5] = m;
    __syncthreads();
    {
        float v0 = red[t & 7];
        #pragma unroll
        for (int o = 4; o > 0; o >>= 1) v0 = fmaxf(v0, __shfl_xor_sync(0xffffffffu, v0, o));
        m = v0;
    }
    __syncthreads();

    float s = 0.f;
    #pragma unroll
    for (int i = 0; i < 4; i++) {
        v[i].x = expf(v[i].x - m); v[i].y = expf(v[i].y - m);
        v[i].z = expf(v[i].z - m); v[i].w = expf(v[i].w - m);
        s += v[i].x + v[i].y + v[i].z + v[i].w;
    }
    #pragma unroll
    for (int o = 16; o > 0; o >>= 1) s += __shfl_xor_sync(0xffffffffu, s, o);
    if ((t & 31) == 0) red[t >> 5] = s;
    __syncthreads();
    {
        float v0 = red[t & 7];
        #pragma unroll
        for (int o = 4; o > 0; o >>= 1) v0 += __shfl_xor_sync(0xffffffffu, v0, o);
        s = v0;
    }

    float inv = 1.0f / s;
    #pragma unroll
    for (int i = 0; i < 4; i++) {
        v[i].x *= inv; v[i].y *= inv; v[i].z *= inv; v[i].w *= inv;
        p[t + 256 * i] = v[i];
    }
}

// ---------------- launch -----------------------------------------------------
extern "C" void kernel_launch(void* const* d_in, const int* in_sizes, int n_in,
                              void* d_out, int out_size) {
    const float* x        = (const float*)d_in[0];
    const int*   ei       = (const int*)d_in[1];
    const float* W1_self  = (const float*)d_in[2];
    const float* W1_neigh = (const float*)d_in[3];
    const float* b1       = (const float*)d_in[4];
    const float* W_in     = (const float*)d_in[5];
    const float* b_in     = (const float*)d_in[6];
    const float* W_out    = (const float*)d_in[7];
    const float* b_out    = (const float*)d_in[8];
    const float* W2_self  = (const float*)d_in[9];
    const float* W2_neigh = (const float*)d_in[10];
    const float* b2       = (const float*)d_in[11];
    const float* Wc       = (const float*)d_in[12];
    const float* bc       = (const float*)d_in[13];

    float* out_x      = (float*)d_out;
    float* out_logits = (float*)d_out + (size_t)NN_ * OUT_;

    float *deg, *agg, *mean, *h1, *qkv, *scores, *attno, *h2;
    cudaGetSymbolAddress((void**)&deg,    g_deg);
    cudaGetSymbolAddress((void**)&agg,    g_agg);
    cudaGetSymbolAddress((void**)&mean,   g_mean);
    cudaGetSymbolAddress((void**)&h1,     g_h1);
    cudaGetSymbolAddress((void**)&qkv,    g_qkv);
    cudaGetSymbolAddress((void**)&scores, g_scores);
    cudaGetSymbolAddress((void**)&attno,  g_attno);
    cudaGetSymbolAddress((void**)&h2,     g_h2);

    const float scale = 1.0f / sqrtf((float)HD_);

    // ---- SAGE 1 ----
    zero_kernel<<<512, 256>>>(deg, NN_);
    zero_kernel<<<2048, 256>>>(agg, NN_ * IN_);
    deg_kernel<<<(EE_ + 255) / 256, 256>>>(ei);
    scatter_add4_kernel<<<(EE_ * (IN_ / 4) + 255) / 256, 256>>>(x, agg, ei, IN_ / 4, IN_);
    mean_kernel<<<(NN_ * IN_ + 255) / 256, 256>>>(agg, mean, IN_);
    {
        dim3 grid((HH_ + 127) / 128, NN_ / 128, 1);
        gemm_nt_v2<<<grid, 256>>>(x, IN_, W1_self, IN_, mean, IN_, W1_neigh, IN_,
                                  b1, h1, HH_, NN_, HH_, IN_, 1.0f, 1, 0, 0, 0);
    }

    // ---- MHA ----
    {
        dim3 grid((3 * HH_ + 127) / 128, NN_ / 128, 1);
        gemm_nt_v2<<<grid, 256>>>(h1, HH_, W_in, HH_, nullptr, 0, nullptr, 0,
                                  b_in, qkv, 3 * HH_, NN_, 3 * HH_, HH_, 1.0f, 0, 0, 0, 0);
    }
    {   // QK^T for all heads: z = head
        dim3 grid(NN_ / 128, NN_ / 128, NHEAD);
        gemm_nt_v2<<<grid, 256>>>(qkv, 3 * HH_, qkv + HH_, 3 * HH_,
                                  nullptr, 0, nullptr, 0, nullptr,
                                  scores, NN_, NN_, NN_, HD_, scale, 0,
                                  (size_t)HD_, (size_t)HD_, (size_t)NN_ * NN_);
    }
    softmax1_kernel<<<NHEAD * NN_, 256>>>(scores);
    zero_kernel<<<2048, 256>>>(attno, NN_ * HH_);
    {   // PV for all heads, split-K
        dim3 grid(1, NN_ / 128, NHEAD * KSPLIT);
        gemm_nn_v2<<<grid, 256>>>(scores, NN_, qkv + 2 * HH_, 3 * HH_,
                                  attno, HH_, NN_, HD_, NN_,
                                  (size_t)NN_ * NN_, (size_t)HD_, (size_t)HD_, KSPLIT);
    }
    {
        dim3 grid((HH_ + 127) / 128, NN_ / 128, 1);
        gemm_nt_v2<<<grid, 256>>>(attno, HH_, W_out, HH_, nullptr, 0, nullptr, 0,
                                  b_out, h2, HH_, NN_, HH_, HH_, 1.0f, 1, 0, 0, 0);
    }

    // ---- SAGE 2 ----
    zero_kernel<<<2048, 256>>>(agg, NN_ * HH_);
    scatter_add4_kernel<<<(EE_ * (HH_ / 4) + 255) / 256, 256>>>(h2, agg, ei, HH_ / 4, HH_);
    mean_kernel<<<(NN_ * HH_ + 255) / 256, 256>>>(agg, mean, HH_);
    {
        dim3 grid((OUT_ + 127) / 128, NN_ / 128, 1);
        gemm_nt_v2<<<grid, 256>>>(h2, HH_, W2_self, HH_, mean, HH_, W2_neigh, HH_,
                                  b2, out_x, OUT_, NN_, OUT_, HH_, 1.0f, 1, 0, 0, 0);
    }

    // ---- classifier ----
    {
        dim3 grid((CC_ + 127) / 128, NN_ / 128, 1);
        gemm_nt_v2<<<grid, 256>>>(out_x, OUT_, Wc, OUT_, nullptr, 0, nullptr, 0,
                                  bc, out_logits, CC_, NN_, CC_, OUT_, 1.0f, 0, 0, 0, 0);
    }
}

// round 3
// speedup vs baseline: 2.7876x; 1.6451x over previous
#include <cuda_runtime.h>
#include <cuda_bf16.h>
#include <math.h>
#include <stdint.h>

#define NN_   4096
#define EE_   131072
#define IN_   500
#define HH_   500
#define OUT_  100
#define CC_   15451
#define CCP_  15488     // CC_ padded to 128
#define NHEAD 4
#define HD_   125
#define HDP_  128

// ---------------- scratch ----------------------------------------------------
__device__ float g_deg[NN_];
__device__ float g_agg[NN_ * HH_];
__device__ float g_mean[NN_ * HH_];
__device__ float g_h1[NN_ * HH_];
__device__ float g_qkv[NN_ * 3 * HH_];
__device__ float g_scores[(size_t)NHEAD * NN_ * NN_];
__device__ float g_attno[NN_ * HH_];
__device__ float g_h2[NN_ * HH_];

__device__ __nv_bfloat16 g_qh[NHEAD * NN_ * HDP_];
__device__ __nv_bfloat16 g_ql[NHEAD * NN_ * HDP_];
__device__ __nv_bfloat16 g_kh[NHEAD * NN_ * HDP_];
__device__ __nv_bfloat16 g_kl[NHEAD * NN_ * HDP_];
__device__ __nv_bfloat16 g_vth[NHEAD * HDP_ * NN_];   // transposed [h][d][n]
__device__ __nv_bfloat16 g_vtl[NHEAD * HDP_ * NN_];
__device__ __nv_bfloat16 g_wch[(size_t)CCP_ * 128];
__device__ __nv_bfloat16 g_wcl[(size_t)CCP_ * 128];

// ---------------- helpers ----------------------------------------------------
__device__ __forceinline__ float4 ldg4(const float* p, int valid) {
    float4 v = make_float4(0.f, 0.f, 0.f, 0.f);
    if (valid >= 4 && ((((uintptr_t)p) & 15) == 0)) {
        v = *(const float4*)p;
    } else {
        if (valid > 0) v.x = __ldg(p);
        if (valid > 1) v.y = __ldg(p + 1);
        if (valid > 2) v.z = __ldg(p + 2);
        if (valid > 3) v.w = __ldg(p + 3);
    }
    return v;
}

__device__ __forceinline__ void splitf(float x, __nv_bfloat16& h, __nv_bfloat16& l) {
    h = __float2bfloat16(x);
    l = __float2bfloat16(x - __bfloat162float(h));
}

// ---------------- elementwise ------------------------------------------------
__global__ void zero_kernel(float* p, int n) {
    int i = blockIdx.x * blockDim.x + threadIdx.x;
    int stride = gridDim.x * blockDim.x;
    for (; i < n; i += stride) p[i] = 0.f;
}

__global__ void deg_kernel(const int* __restrict__ ei) {
    int e = blockIdx.x * blockDim.x + threadIdx.x;
    if (e < EE_) atomicAdd(&g_deg[ei[EE_ + e]], 1.0f);
}

__global__ void scatter_add4_kernel(const float* __restrict__ feat,
                                    float* __restrict__ agg,
                                    const int* __restrict__ ei, int F4, int F) {
    int idx = blockIdx.x * blockDim.x + threadIdx.x;
    int total = EE_ * F4;
    if (idx >= total) return;
    int e = idx / F4;
    int g = idx - e * F4;
    int s = __ldg(&ei[e]);
    int d = __ldg(&ei[EE_ + e]);
    float4 v = *((const float4*)(feat + (size_t)s * F) + g);
    float* o = agg + (size_t)d * F + g * 4;
    atomicAdd(o + 0, v.x);
    atomicAdd(o + 1, v.y);
    atomicAdd(o + 2, v.z);
    atomicAdd(o + 3, v.w);
}

__global__ void mean_kernel(const float* __restrict__ agg,
                            float* __restrict__ mean, int F) {
    int idx = blockIdx.x * blockDim.x + threadIdx.x;
    if (idx >= NN_ * F) return;
    int row = idx / F;
    mean[idx] = agg[idx] / fmaxf(g_deg[row], 1.0f);
}

// ---------------- conversion kernels -----------------------------------------
__global__ void convert_qk_kernel(const float* __restrict__ qkv) {
    int idx = blockIdx.x * blockDim.x + threadIdx.x;
    if (idx >= NHEAD * NN_ * HDP_) return;
    int d = idx & 127;
    int n = (idx >> 7) & (NN_ - 1);
    int h = idx >> 19;
    float q = 0.f, k = 0.f;
    if (d < HD_) {
        const float* row = qkv + (size_t)n * (3 * HH_) + h * HD_ + d;
        q = row[0];
        k = row[HH_];
    }
    splitf(q, g_qh[idx], g_ql[idx]);
    splitf(k, g_kh[idx], g_kl[idx]);
}

__global__ void convert_v_kernel(const float* __restrict__ qkv) {
    int idx = blockIdx.x * blockDim.x + threadIdx.x;
    if (idx >= NHEAD * HDP_ * NN_) return;
    int n = idx & (NN_ - 1);
    int d = (idx >> 12) & 127;
    int h = idx >> 19;
    float v = 0.f;
    if (d < HD_) v = qkv[(size_t)n * (3 * HH_) + 2 * HH_ + h * HD_ + d];
    splitf(v, g_vth[idx], g_vtl[idx]);
}

__global__ void convert_wc_kernel(const float* __restrict__ Wc) {
    int idx = blockIdx.x * blockDim.x + threadIdx.x;
    if (idx >= CCP_ * 128) return;
    int d = idx & 127;
    int n = idx >> 7;
    float v = (n < CC_ && d < OUT_) ? Wc[(size_t)n * OUT_ + d] : 0.f;
    splitf(v, g_wch[idx], g_wcl[idx]);
}

// ---------------- bf16-split tensor-core GEMM (NT) ----------------------------
// C[M=4096, N] = alpha*(A @ B^T) [+ bias], A split hi/lo [M,K] bf16 row-major
// (or fp32 split on load), B split hi/lo [N,K] bf16 row-major.
// 3-pass: hi*hi + hi*lo + lo*hi. CTA 128x128, k-chunk 32, 8 warps (4m x 2n).
// mode 0: store C[row*ldc+col] (col<Nfull guard), mode 1: atomicAdd compact
// into C[row*500 + h*125 + col] for col<125 (PV epilogue).
#define MMA_BF16(d, a, b) \
  asm volatile("mma.sync.aligned.m16n8k16.row.col.f32.bf16.bf16.f32 " \
   "{%0,%1,%2,%3},{%4,%5,%6,%7},{%8,%9},{%0,%1,%2,%3};" \
   : "+f"((d)[0]), "+f"((d)[1]), "+f"((d)[2]), "+f"((d)[3]) \
   : "r"((a)[0]), "r"((a)[1]), "r"((a)[2]), "r"((a)[3]), "r"((b)[0]), "r"((b)[1]))

__global__ __launch_bounds__(256, 1)
void gemm_mma_nt(const void* __restrict__ A_, const void* __restrict__ Alo_,
                 int lda,
                 const __nv_bfloat16* __restrict__ Bhi_,
                 const __nv_bfloat16* __restrict__ Blo_, int ldb,
                 const float* __restrict__ bias,
                 float* __restrict__ C, int ldc,
                 int Nfull, int K, int kValidA, float alpha,
                 int afp32, int mode,
                 size_t zsA, size_t zsB, size_t zsC, int ksplit) {
    __shared__ __align__(16) __nv_bfloat16 sAh[128 * 40];
    __shared__ __align__(16) __nv_bfloat16 sAl[128 * 40];
    __shared__ __align__(16) __nv_bfloat16 sBh[128 * 40];
    __shared__ __align__(16) __nv_bfloat16 sBl[128 * 40];

    const int tid  = threadIdx.x;
    const int lane = tid & 31;
    const int wid  = tid >> 5;
    const int wm   = wid & 3;     // 0..3 -> m offset wm*32
    const int wn   = wid >> 2;    // 0..1 -> n offset wn*64
    const int bm   = blockIdx.y * 128;
    const int bn   = blockIdx.x * 128;
    const int z    = blockIdx.z;
    const int h    = z / ksplit;
    const int ks   = z - h * ksplit;
    const int klen = K / ksplit;
    const int kb   = ks * klen;
    const int kValid = kValidA - kb;

    const float* Af = (const float*)A_;
    const __nv_bfloat16* Ahi = (const __nv_bfloat16*)A_;
    const __nv_bfloat16* Alo = (const __nv_bfloat16*)Alo_;
    if (afp32) Af = Af + h * zsA + kb;
    else { Ahi += h * zsA + kb; Alo += h * zsA + kb; }
    const __nv_bfloat16* Bhi = Bhi_ + h * zsB + kb;
    const __nv_bfloat16* Blo = Blo_ + h * zsB + kb;
    C += h * zsC;

    float acc[2][8][4];
    #pragma unroll
    for (int i = 0; i < 2; i++)
        #pragma unroll
        for (int j = 0; j < 8; j++)
            #pragma unroll
            for (int q = 0; q < 4; q++) acc[i][j][q] = 0.f;

    uint4 stA[4], stB[4];

    // ---- prefetch lambda ----
    auto prefetch = [&](int k0) {
        if (afp32) {
            #pragma unroll
            for (int i = 0; i < 4; i++) {
                int l = tid + i * 256;
                int r = l >> 3, g4 = l & 7;
                float4 v = make_float4(0.f, 0.f, 0.f, 0.f);
                if (k0 + g4 * 4 < kValid)
                    v = *(const float4*)(Af + (size_t)(bm + r) * lda + k0 + g4 * 4);
                stA[i] = *(uint4*)&v;
            }
        } else {
            #pragma unroll
            for (int i = 0; i < 2; i++) {
                int l = tid + i * 256;
                int r = l >> 2, g = l & 3;
                stA[i]     = *(const uint4*)(Ahi + (size_t)(bm + r) * lda + k0 + g * 8);
                stA[i + 2] = *(const uint4*)(Alo + (size_t)(bm + r) * lda + k0 + g * 8);
            }
        }
        #pragma unroll
        for (int i = 0; i < 2; i++) {
            int l = tid + i * 256;
            int r = l >> 2, g = l & 3;
            if (bn + r < Nfull) {
                stB[i]     = *(const uint4*)(Bhi + (size_t)(bn + r) * ldb + k0 + g * 8);
                stB[i + 2] = *(const uint4*)(Blo + (size_t)(bn + r) * ldb + k0 + g * 8);
            } else {
                stB[i] = make_uint4(0, 0, 0, 0);
                stB[i + 2] = make_uint4(0, 0, 0, 0);
            }
        }
    };

    auto store_smem = [&]() {
        if (afp32) {
            #pragma unroll
            for (int i = 0; i < 4; i++) {
                int l = tid + i * 256;
                int r = l >> 3, g4 = l & 7;
                float4 v = *(float4*)&stA[i];
                __nv_bfloat16 h0, l0, h1, l1, h2, l2, h3, l3;
                splitf(v.x, h0, l0); splitf(v.y, h1, l1);
                splitf(v.z, h2, l2); splitf(v.w, h3, l3);
                __nv_bfloat162* ph = (__nv_bfloat162*)(sAh + r * 40 + g4 * 4);
                __nv_bfloat162* pl = (__nv_bfloat162*)(sAl + r * 40 + g4 * 4);
                __nv_bfloat162 t;
                t.x = h0; t.y = h1; ph[0] = t;
                t.x = h2; t.y = h3; ph[1] = t;
                t.x = l0; t.y = l1; pl[0] = t;
                t.x = l2; t.y = l3; pl[1] = t;
            }
        } else {
            #pragma unroll
            for (int i = 0; i < 2; i++) {
                int l = tid + i * 256;
                int r = l >> 2, g = l & 3;
                *(uint4*)(sAh + r * 40 + g * 8) = stA[i];
                *(uint4*)(sAl + r * 40 + g * 8) = stA[i + 2];
            }
        }
        #pragma unroll
        for (int i = 0; i < 2; i++) {
            int l = tid + i * 256;
            int r = l >> 2, g = l & 3;
            *(uint4*)(sBh + r * 40 + g * 8) = stB[i];
            *(uint4*)(sBl + r * 40 + g * 8) = stB[i + 2];
        }
    };

    prefetch(0);
    for (int k0 = 0; k0 < klen; k0 += 32) {
        store_smem();
        __syncthreads();
        if (k0 + 32 < klen) prefetch(k0 + 32);

        #pragma unroll
        for (int ksf = 0; ksf < 2; ++ksf) {
            uint32_t ah[2][4], al[2][4];
            #pragma unroll
            for (int mt = 0; mt < 2; ++mt) {
                int ar = wm * 32 + mt * 16 + (lane >> 2);
                int off = ar * 40 + ksf * 16 + ((lane & 3) << 1);
                ah[mt][0] = *(const uint32_t*)(sAh + off);
                ah[mt][1] = *(const uint32_t*)(sAh + off + 8 * 40);
                ah[mt][2] = *(const uint32_t*)(sAh + off + 8);
                ah[mt][3] = *(const uint32_t*)(sAh + off + 8 * 40 + 8);
                al[mt][0] = *(const uint32_t*)(sAl + off);
                al[mt][1] = *(const uint32_t*)(sAl + off + 8 * 40);
                al[mt][2] = *(const uint32_t*)(sAl + off + 8);
                al[mt][3] = *(const uint32_t*)(sAl + off + 8 * 40 + 8);
            }
            #pragma unroll
            for (int nt = 0; nt < 8; ++nt) {
                int br = wn * 64 + nt * 8 + (lane >> 2);
                int off = br * 40 + ksf * 16 + ((lane & 3) << 1);
                uint32_t bh[2], bl[2];
                bh[0] = *(const uint32_t*)(sBh + off);
                bh[1] = *(const uint32_t*)(sBh + off + 8);
                bl[0] = *(const uint32_t*)(sBl + off);
                bl[1] = *(const uint32_t*)(sBl + off + 8);
                #pragma unroll
                for (int mt = 0; mt < 2; ++mt) {
                    MMA_BF16(acc[mt][nt], ah[mt], bh);
                    MMA_BF16(acc[mt][nt], ah[mt], bl);
                    MMA_BF16(acc[mt][nt], al[mt], bh);
                }
            }
        }
        __syncthreads();
    }

    // ---- epilogue ----
    if (mode == 0) {
        #pragma unroll
        for (int mt = 0; mt < 2; ++mt) {
            int row = bm + wm * 32 + mt * 16 + (lane >> 2);
            #pragma unroll
            for (int nt = 0; nt < 8; ++nt) {
                int gc = bn + wn * 64 + nt * 8 + ((lane & 3) << 1);
                #pragma unroll
                for (int j = 0; j < 2; ++j) {
                    if (gc + j < Nfull) {
                        float bsv = bias ? bias[gc + j] : 0.f;
                        C[(size_t)row * ldc + gc + j]       = alpha * acc[mt][nt][j]     + bsv;
                        C[(size_t)(row + 8) * ldc + gc + j] = alpha * acc[mt][nt][j + 2] + bsv;
                    }
                }
            }
        }
    } else {
        int hofs = h * HD_;
        #pragma unroll
        for (int mt = 0; mt < 2; ++mt) {
            int row = bm + wm * 32 + mt * 16 + (lane >> 2);
            #pragma unroll
            for (int nt = 0; nt < 8; ++nt) {
                int gc = wn * 64 + nt * 8 + ((lane & 3) << 1);
                #pragma unroll
                for (int j = 0; j < 2; ++j) {
                    if (gc + j < HD_) {
                        atomicAdd(&C[(size_t)row * HH_ + hofs + gc + j], acc[mt][nt][j]);
                        atomicAdd(&C[(size_t)(row + 8) * HH_ + hofs + gc + j], acc[mt][nt][j + 2]);
                    }
                }
            }
        }
    }
}

// ---------------- SIMT GEMM NT (SAGE / projections) ---------------------------
__global__ __launch_bounds__(256)
void gemm_nt_v2(const float* __restrict__ A1, int lda1,
                const float* __restrict__ B1, int ldb1,
                const float* __restrict__ A2, int lda2,
                const float* __restrict__ B2, int ldb2,
                const float* __restrict__ bias,
                float* __restrict__ C, int ldc,
                int M, int N, int K, float alpha, int relu) {
    __shared__ float As[2][8][132];
    __shared__ float Bs[2][8][132];
    int t  = threadIdx.x;
    int tx = t & 15, ty = t >> 4;
    int bm = blockIdx.y * 128, bn = blockIdx.x * 128;

    float acc[8][8];
    #pragma unroll
    for (int i = 0; i < 8; i++)
        #pragma unroll
        for (int j = 0; j < 8; j++) acc[i][j] = 0.f;

    const int row = t >> 1;
    const int kq  = (t & 1) * 4;
    const bool am = (bm + row) < M;
    const bool bnok = (bn + row) < N;

    for (int p = 0; p < 2; ++p) {
        const float* A = p ? A2 : A1;
        if (A == nullptr) break;
        const float* B = p ? B2 : B1;
        int lda = p ? lda2 : lda1;
        int ldb = p ? ldb2 : ldb1;

        const float* ap = A + (size_t)(bm + row) * lda + kq;
        const float* bp = B + (size_t)(bn + row) * ldb + kq;

        __syncthreads();
        {
            int avail = K - kq;
            float4 va = ldg4(ap, am ? avail : 0);
            float4 vb = ldg4(bp, bnok ? avail : 0);
            As[0][kq + 0][row] = va.x; As[0][kq + 1][row] = va.y;
            As[0][kq + 2][row] = va.z; As[0][kq + 3][row] = va.w;
            Bs[0][kq + 0][row] = vb.x; Bs[0][kq + 1][row] = vb.y;
            Bs[0][kq + 2][row] = vb.z; Bs[0][kq + 3][row] = vb.w;
        }
        __syncthreads();

        int buf = 0;
        for (int k0 = 0; k0 < K; k0 += 8) {
            int kn = k0 + 8;
            bool have = kn < K;
            float4 va, vb;
            if (have) {
                int avail = K - (kn + kq);
                va = ldg4(ap + kn, am ? avail : 0);
                vb = ldg4(bp + kn, bnok ? avail : 0);
            }
            #pragma unroll
            for (int kk = 0; kk < 8; ++kk) {
                float4 a0 = *(const float4*)&As[buf][kk][ty * 8];
                float4 a1 = *(const float4*)&As[buf][kk][ty * 8 + 4];
                float4 b0 = *(const float4*)&Bs[buf][kk][tx * 8];
                float4 b1 = *(const float4*)&Bs[buf][kk][tx * 8 + 4];
                float a[8] = {a0.x, a0.y, a0.z, a0.w, a1.x, a1.y, a1.z, a1.w};
                float b[8] = {b0.x, b0.y, b0.z, b0.w, b1.x, b1.y, b1.z, b1.w};
                #pragma unroll
                for (int i = 0; i < 8; i++)
                    #pragma unroll
                    for (int j = 0; j < 8; j++)
                        acc[i][j] = fmaf(a[i], b[j], acc[i][j]);
            }
            if (have) {
                int nb = buf ^ 1;
                As[nb][kq + 0][row] = va.x; As[nb][kq + 1][row] = va.y;
                As[nb][kq + 2][row] = va.z; As[nb][kq + 3][row] = va.w;
                Bs[nb][kq + 0][row] = vb.x; Bs[nb][kq + 1][row] = vb.y;
                Bs[nb][kq + 2][row] = vb.z; Bs[nb][kq + 3][row] = vb.w;
                __syncthreads();
                buf = nb;
            }
        }
    }

    #pragma unroll
    for (int i = 0; i < 8; i++) {
        int gm = bm + ty * 8 + i;
        if (gm >= M) continue;
        #pragma unroll
        for (int j = 0; j < 8; j++) {
            int gn = bn + tx * 8 + j;
            if (gn >= N) continue;
            float v = alpha * acc[i][j];
            if (bias) v += bias[gn];
            if (relu) v = fmaxf(v, 0.f);
            C[(size_t)gm * ldc + gn] = v;
        }
    }
}

// ---------------- one-pass softmax (row length 4096) --------------------------
__global__ __launch_bounds__(256)
void softmax1_kernel(float* __restrict__ S) {
    size_t row = blockIdx.x;
    float4* p = (float4*)(S + row * (size_t)NN_);
    int t = threadIdx.x;
    __shared__ float red[8];

    float4 v[4];
    #pragma unroll
    for (int i = 0; i < 4; i++) v[i] = p[t + 256 * i];

    float m = -1e30f;
    #pragma unroll
    for (int i = 0; i < 4; i++)
        m = fmaxf(m, fmaxf(fmaxf(v[i].x, v[i].y), fmaxf(v[i].z, v[i].w)));
    #pragma unroll
    for (int o = 16; o > 0; o >>= 1) m = fmaxf(m, __shfl_xor_sync(0xffffffffu, m, o));
    if ((t & 31) == 0) red[t >> 5] = m;
    __syncthreads();
    {
        float v0 = red[t & 7];
        #pragma unroll
        for (int o = 4; o > 0; o >>= 1) v0 = fmaxf(v0, __shfl_xor_sync(0xffffffffu, v0, o));
        m = v0;
    }
    __syncthreads();

    float s = 0.f;
    #pragma unroll
    for (int i = 0; i < 4; i++) {
        v[i].x = expf(v[i].x - m); v[i].y = expf(v[i].y - m);
        v[i].z = expf(v[i].z - m); v[i].w = expf(v[i].w - m);
        s += v[i].x + v[i].y + v[i].z + v[i].w;
    }
    #pragma unroll
    for (int o = 16; o > 0; o >>= 1) s += __shfl_xor_sync(0xffffffffu, s, o);
    if ((t & 31) == 0) red[t >> 5] = s;
    __syncthreads();
    {
        float v0 = red[t & 7];
        #pragma unroll
        for (int o = 4; o > 0; o >>= 1) v0 += __shfl_xor_sync(0xffffffffu, v0, o);
        s = v0;
    }

    float inv = 1.0f / s;
    #pragma unroll
    for (int i = 0; i < 4; i++) {
        v[i].x *= inv; v[i].y *= inv; v[i].z *= inv; v[i].w *= inv;
        p[t + 256 * i] = v[i];
    }
}

// ---------------- launch -----------------------------------------------------
extern "C" void kernel_launch(void* const* d_in, const int* in_sizes, int n_in,
                              void* d_out, int out_size) {
    const float* x        = (const float*)d_in[0];
    const int*   ei       = (const int*)d_in[1];
    const float* W1_self  = (const float*)d_in[2];
    const float* W1_neigh = (const float*)d_in[3];
    const float* b1       = (const float*)d_in[4];
    const float* W_in     = (const float*)d_in[5];
    const float* b_in     = (const float*)d_in[6];
    const float* W_out    = (const float*)d_in[7];
    const float* b_out    = (const float*)d_in[8];
    const float* W2_self  = (const float*)d_in[9];
    const float* W2_neigh = (const float*)d_in[10];
    const float* b2       = (const float*)d_in[11];
    const float* Wc       = (const float*)d_in[12];
    const float* bc       = (const float*)d_in[13];

    float* out_x      = (float*)d_out;
    float* out_logits = (float*)d_out + (size_t)NN_ * OUT_;

    float *deg, *agg, *mean, *h1, *qkv, *scores, *attno, *h2;
    cudaGetSymbolAddress((void**)&deg,    g_deg);
    cudaGetSymbolAddress((void**)&agg,    g_agg);
    cudaGetSymbolAddress((void**)&mean,   g_mean);
    cudaGetSymbolAddress((void**)&h1,     g_h1);
    cudaGetSymbolAddress((void**)&qkv,    g_qkv);
    cudaGetSymbolAddress((void**)&scores, g_scores);
    cudaGetSymbolAddress((void**)&attno,  g_attno);
    cudaGetSymbolAddress((void**)&h2,     g_h2);

    __nv_bfloat16 *qh, *ql, *kh, *kl, *vth, *vtl, *wch, *wcl;
    cudaGetSymbolAddress((void**)&qh,  g_qh);
    cudaGetSymbolAddress((void**)&ql,  g_ql);
    cudaGetSymbolAddress((void**)&kh,  g_kh);
    cudaGetSymbolAddress((void**)&kl,  g_kl);
    cudaGetSymbolAddress((void**)&vth, g_vth);
    cudaGetSymbolAddress((void**)&vtl, g_vtl);
    cudaGetSymbolAddress((void**)&wch, g_wch);
    cudaGetSymbolAddress((void**)&wcl, g_wcl);

    const float scale = 1.0f / sqrtf((float)HD_);

    // ---- SAGE 1 ----
    zero_kernel<<<512, 256>>>(deg, NN_);
    zero_kernel<<<2048, 256>>>(agg, NN_ * IN_);
    deg_kernel<<<(EE_ + 255) / 256, 256>>>(ei);
    scatter_add4_kernel<<<(EE_ * (IN_ / 4) + 255) / 256, 256>>>(x, agg, ei, IN_ / 4, IN_);
    mean_kernel<<<(NN_ * IN_ + 255) / 256, 256>>>(agg, mean, IN_);
    {
        dim3 grid((HH_ + 127) / 128, NN_ / 128, 1);
        gemm_nt_v2<<<grid, 256>>>(x, IN_, W1_self, IN_, mean, IN_, W1_neigh, IN_,
                                  b1, h1, HH_, NN_, HH_, IN_, 1.0f, 1);
    }

    // ---- MHA: qkv projection (SIMT) ----
    {
        dim3 grid((3 * HH_ + 127) / 128, NN_ / 128, 1);
        gemm_nt_v2<<<grid, 256>>>(h1, HH_, W_in, HH_, nullptr, 0, nullptr, 0,
                                  b_in, qkv, 3 * HH_, NN_, 3 * HH_, HH_, 1.0f, 0);
    }
    // convert q/k/v to hi/lo bf16 (padded, head-contiguous; v transposed)
    convert_qk_kernel<<<(NHEAD * NN_ * HDP_ + 255) / 256, 256>>>(qkv);
    convert_v_kernel<<<(NHEAD * HDP_ * NN_ + 255) / 256, 256>>>(qkv);

    // ---- QK^T (tensor core, 3-pass bf16 split) ----
    {
        dim3 grid(NN_ / 128, NN_ / 128, NHEAD);
        gemm_mma_nt<<<grid, 256>>>(qh, ql, HDP_, kh, kl, HDP_,
                                   nullptr, scores, NN_,
                                   NN_, HDP_, HDP_, scale, 0, 0,
                                   (size_t)NN_ * HDP_, (size_t)NN_ * HDP_,
                                   (size_t)NN_ * NN_, 1);
    }
    softmax1_kernel<<<NHEAD * NN_, 256>>>(scores);

    // ---- PV (tensor core, A=fp32 attn split on load, split-K=2) ----
    zero_kernel<<<2048, 256>>>(attno, NN_ * HH_);
    {
        dim3 grid(1, NN_ / 128, NHEAD * 2);
        gemm_mma_nt<<<grid, 256>>>(scores, nullptr, NN_, vth, vtl, NN_,
                                   nullptr, attno, HH_,
                                   HDP_, NN_, NN_, 1.0f, 1, 1,
                                   (size_t)NN_ * NN_, (size_t)HDP_ * NN_,
                                   0, 2);
    }
    // ---- out projection (SIMT) ----
    {
        dim3 grid((HH_ + 127) / 128, NN_ / 128, 1);
        gemm_nt_v2<<<grid, 256>>>(attno, HH_, W_out, HH_, nullptr, 0, nullptr, 0,
                                  b_out, h2, HH_, NN_, HH_, HH_, 1.0f, 1);
    }

    // ---- SAGE 2 ----
    zero_kernel<<<2048, 256>>>(agg, NN_ * HH_);
    scatter_add4_kernel<<<(EE_ * (HH_ / 4) + 255) / 256, 256>>>(h2, agg, ei, HH_ / 4, HH_);
    mean_kernel<<<(NN_ * HH_ + 255) / 256, 256>>>(agg, mean, HH_);
    {
        dim3 grid((OUT_ + 127) / 128, NN_ / 128, 1);
        gemm_nt_v2<<<grid, 256>>>(h2, HH_, W2_self, HH_, mean, HH_, W2_neigh, HH_,
                                  b2, out_x, OUT_, NN_, OUT_, HH_, 1.0f, 1);
    }

    // ---- classifier (tensor core, A=out_x fp32 split, B=Wc pre-split) ----
    convert_wc_kernel<<<(CCP_ * 128 + 255) / 256, 256>>>(Wc);
    {
        dim3 grid(CCP_ / 128, NN_ / 128, 1);
        gemm_mma_nt<<<grid, 256>>>(out_x, nullptr, OUT_, wch, wcl, 128,
                                   bc, out_logits, CC_,
                                   CC_, 128, OUT_, 1.0f, 1, 0,
                                   0, 0, 0, 1);
    }
}

// round 4
// speedup vs baseline: 3.4127x; 1.2242x over previous
#include <cuda_runtime.h>
#include <cuda_bf16.h>
#include <math.h>
#include <stdint.h>

#define NN_   4096
#define EE_   131072
#define IN_   500
#define HH_   500
#define OUT_  100
#define CC_   15451
#define CCP_  15488
#define NHEAD 4
#define HD_   125
#define HDP_  128
#define KP500 512      // K=500 padded to 512

// ---------------- scratch ----------------------------------------------------
__device__ int   g_degi[NN_];
__device__ int   g_off[NN_ + 1];
__device__ int   g_cur[NN_];
__device__ int   g_csr[EE_];
__device__ float g_mean[NN_ * HH_];
__device__ float g_h1[NN_ * HH_];
__device__ float g_qkv[NN_ * 3 * HH_];
__device__ float g_scores[(size_t)NHEAD * NN_ * NN_];
__device__ float2 g_stats[NHEAD * NN_];
__device__ float g_attno[NN_ * HH_];
__device__ float g_h2[NN_ * HH_];
__device__ float g_tmp2[NN_ * OUT_];

__device__ __nv_bfloat16 g_qh[NHEAD * NN_ * HDP_];
__device__ __nv_bfloat16 g_ql[NHEAD * NN_ * HDP_];
__device__ __nv_bfloat16 g_kh[NHEAD * NN_ * HDP_];
__device__ __nv_bfloat16 g_kl[NHEAD * NN_ * HDP_];
__device__ __nv_bfloat16 g_vth[NHEAD * HDP_ * NN_];
__device__ __nv_bfloat16 g_vtl[NHEAD * HDP_ * NN_];

__device__ __nv_bfloat16 g_w1sh[HH_ * KP500], g_w1sl[HH_ * KP500];
__device__ __nv_bfloat16 g_w1nh[HH_ * KP500], g_w1nl[HH_ * KP500];
__device__ __nv_bfloat16 g_winh[3 * HH_ * KP500], g_winl[3 * HH_ * KP500];
__device__ __nv_bfloat16 g_woh[HH_ * KP500], g_wol[HH_ * KP500];
__device__ __nv_bfloat16 g_w2sh[OUT_ * KP500], g_w2sl[OUT_ * KP500];
__device__ __nv_bfloat16 g_w2nh[OUT_ * KP500], g_w2nl[OUT_ * KP500];
__device__ __nv_bfloat16 g_wch[(size_t)CC_ * 128], g_wcl[(size_t)CC_ * 128];

// ---------------- helpers ----------------------------------------------------
__device__ __forceinline__ void splitf(float x, __nv_bfloat16& h, __nv_bfloat16& l) {
    h = __float2bfloat16(x);
    l = __float2bfloat16(x - __bfloat162float(h));
}

// ---------------- small kernels ----------------------------------------------
__global__ void zero_f(float* p, int n) {
    int i = blockIdx.x * blockDim.x + threadIdx.x;
    int stride = gridDim.x * blockDim.x;
    for (; i < n; i += stride) p[i] = 0.f;
}
__global__ void zero_i(int* p, int n) {
    int i = blockIdx.x * blockDim.x + threadIdx.x;
    if (i < n) p[i] = 0;
}
__global__ void count_deg(const int* __restrict__ ei) {
    int e = blockIdx.x * blockDim.x + threadIdx.x;
    if (e < EE_) atomicAdd(&g_degi[ei[EE_ + e]], 1);
}
__global__ __launch_bounds__(1024) void scan_offsets() {
    __shared__ int s[1024];
    int t = threadIdx.x;
    int base = t * 4;
    int v[4], lp[4];
    int sum = 0;
    #pragma unroll
    for (int i = 0; i < 4; i++) { v[i] = g_degi[base + i]; lp[i] = sum; sum += v[i]; }
    s[t] = sum;
    __syncthreads();
    for (int off = 1; off < 1024; off <<= 1) {
        int x = (t >= off) ? s[t - off] : 0;
        __syncthreads();
        s[t] += x;
        __syncthreads();
    }
    int excl = (t > 0) ? s[t - 1] : 0;
    #pragma unroll
    for (int i = 0; i < 4; i++) {
        int o = excl + lp[i];
        g_off[base + i] = o;
        g_cur[base + i] = o;
    }
    if (t == 1023) g_off[NN_] = s[1023];
}
__global__ void csr_fill(const int* __restrict__ ei) {
    int e = blockIdx.x * blockDim.x + threadIdx.x;
    if (e >= EE_) return;
    int d = ei[EE_ + e];
    int pos = atomicAdd(&g_cur[d], 1);
    g_csr[pos] = ei[e];
}

// gather-mean: one CTA per node, thread t handles float4 group t (F4 groups)
__global__ __launch_bounds__(128) void gather_mean(const float* __restrict__ feat,
                                                   float* __restrict__ mean, int F4) {
    int node = blockIdx.x;
    int t = threadIdx.x;
    if (t >= F4) return;
    int beg = g_off[node], end = g_off[node + 1];
    const float4* f4 = (const float4*)feat;
    float4 acc = make_float4(0.f, 0.f, 0.f, 0.f);
    int e = beg;
    for (; e + 1 < end; e += 2) {
        int s0 = __ldg(&g_csr[e]);
        int s1 = __ldg(&g_csr[e + 1]);
        float4 v0 = f4[(size_t)s0 * F4 + t];
        float4 v1 = f4[(size_t)s1 * F4 + t];
        acc.x += v0.x; acc.y += v0.y; acc.z += v0.z; acc.w += v0.w;
        acc.x += v1.x; acc.y += v1.y; acc.z += v1.z; acc.w += v1.w;
    }
    if (e < end) {
        int s0 = __ldg(&g_csr[e]);
        float4 v0 = f4[(size_t)s0 * F4 + t];
        acc.x += v0.x; acc.y += v0.y; acc.z += v0.z; acc.w += v0.w;
    }
    float inv = 1.0f / fmaxf((float)(end - beg), 1.0f);
    ((float4*)mean)[(size_t)node * F4 + t] =
        make_float4(acc.x * inv, acc.y * inv, acc.z * inv, acc.w * inv);
}

// split fp32 weight [Nr,Kr] -> hi/lo bf16 [Nr,Kpad] (zero-padded K)
__global__ void split_w(const float* __restrict__ W, int Nr, int Kr, int Kpad,
                        __nv_bfloat16* __restrict__ hi, __nv_bfloat16* __restrict__ lo) {
    long long idx = (long long)blockIdx.x * blockDim.x + threadIdx.x;
    long long total = (long long)Nr * Kpad;
    if (idx >= total) return;
    int k = (int)(idx % Kpad);
    long long n = idx / Kpad;
    float v = (k < Kr) ? W[n * Kr + k] : 0.f;
    splitf(v, hi[idx], lo[idx]);
}

__global__ void convert_qk_kernel(const float* __restrict__ qkv) {
    int idx = blockIdx.x * blockDim.x + threadIdx.x;
    if (idx >= NHEAD * NN_ * HDP_) return;
    int d = idx & 127;
    int n = (idx >> 7) & (NN_ - 1);
    int h = idx >> 19;
    float q = 0.f, k = 0.f;
    if (d < HD_) {
        const float* row = qkv + (size_t)n * (3 * HH_) + h * HD_ + d;
        q = row[0];
        k = row[HH_];
    }
    splitf(q, g_qh[idx], g_ql[idx]);
    splitf(k, g_kh[idx], g_kl[idx]);
}

__global__ void convert_v_kernel(const float* __restrict__ qkv) {
    int idx = blockIdx.x * blockDim.x + threadIdx.x;
    if (idx >= NHEAD * HDP_ * NN_) return;
    int n = idx & (NN_ - 1);
    int d = (idx >> 12) & 127;
    int h = idx >> 19;
    float v = 0.f;
    if (d < HD_) v = qkv[(size_t)n * (3 * HH_) + 2 * HH_ + h * HD_ + d];
    splitf(v, g_vth[idx], g_vtl[idx]);
}

// per-row softmax stats: m and 1/sum(exp(x-m)); rows = NHEAD*NN_, len 4096
__global__ __launch_bounds__(256) void stats_kernel(const float* __restrict__ S) {
    size_t row = blockIdx.x;
    const float4* p = (const float4*)(S + row * (size_t)NN_);
    int t = threadIdx.x;
    __shared__ float red[8];
    float4 v[4];
    #pragma unroll
    for (int i = 0; i < 4; i++) v[i] = p[t + 256 * i];
    float m = -1e30f;
    #pragma unroll
    for (int i = 0; i < 4; i++)
        m = fmaxf(m, fmaxf(fmaxf(v[i].x, v[i].y), fmaxf(v[i].z, v[i].w)));
    #pragma unroll
    for (int o = 16; o > 0; o >>= 1) m = fmaxf(m, __shfl_xor_sync(0xffffffffu, m, o));
    if ((t & 31) == 0) red[t >> 5] = m;
    __syncthreads();
    {
        float v0 = red[t & 7];
        #pragma unroll
        for (int o = 4; o > 0; o >>= 1) v0 = fmaxf(v0, __shfl_xor_sync(0xffffffffu, v0, o));
        m = v0;
    }
    float s = 0.f;
    #pragma unroll
    for (int i = 0; i < 4; i++) {
        s += __expf(v[i].x - m) + __expf(v[i].y - m) +
             __expf(v[i].z - m) + __expf(v[i].w - m);
    }
    #pragma unroll
    for (int o = 16; o > 0; o >>= 1) s += __shfl_xor_sync(0xffffffffu, s, o);
    if ((t & 31) == 0) red[t >> 5] = s;
    __syncthreads();
    {
        float v0 = red[t & 7];
        #pragma unroll
        for (int o = 4; o > 0; o >>= 1) v0 += __shfl_xor_sync(0xffffffffu, v0, o);
        s = v0;
    }
    if (t == 0) g_stats[row] = make_float2(m, 1.0f / s);
}

__global__ void bias_relu_kernel(const float* __restrict__ in,
                                 const float* __restrict__ b,
                                 float* __restrict__ out, int n, int cols) {
    int i = blockIdx.x * blockDim.x + threadIdx.x;
    if (i >= n) return;
    out[i] = fmaxf(in[i] + b[i % cols], 0.f);
}

// ---------------- unified bf16-split tensor-core GEMM (NT) --------------------
#define MMA_BF16(d, a, b) \
  asm volatile("mma.sync.aligned.m16n8k16.row.col.f32.bf16.bf16.f32 " \
   "{%0,%1,%2,%3},{%4,%5,%6,%7},{%8,%9},{%0,%1,%2,%3};" \
   : "+f"((d)[0]), "+f"((d)[1]), "+f"((d)[2]), "+f"((d)[3]) \
   : "r"((a)[0]), "r"((a)[1]), "r"((a)[2]), "r"((a)[3]), "r"((b)[0]), "r"((b)[1]))

// A: fp32 (split-on-load, optional exp transform, optional 2nd pair A2/B2pair)
//    or pre-split bf16 (A_=hi, Alo_=lo). B: pre-split bf16 pairs.
// mode 0: C[row*ldc + bn+col] = alpha*acc + bias, opt relu (col<Nfull guard)
// mode 1: atomicAdd C[row*ldc + h*HD_ + col], col<Nfull guard (no bias/alpha)
__global__ __launch_bounds__(256, 1)
void gemm_mma_v2(const void* __restrict__ A_, const void* __restrict__ Alo_,
                 const float* __restrict__ A2f, int lda,
                 const __nv_bfloat16* __restrict__ B1h, const __nv_bfloat16* __restrict__ B1l,
                 const __nv_bfloat16* __restrict__ B2h, const __nv_bfloat16* __restrict__ B2l,
                 int ldb,
                 const float2* __restrict__ rowstats,
                 const float* __restrict__ bias,
                 float* __restrict__ C, int ldc,
                 int Nfull, int Kpad, int kValidA, float alpha,
                 int afp32, int relu, int mode,
                 size_t zsA, size_t zsB, size_t zsC, int ksplit) {
    __shared__ __align__(16) __nv_bfloat16 sAh[128 * 40];
    __shared__ __align__(16) __nv_bfloat16 sAl[128 * 40];
    __shared__ __align__(16) __nv_bfloat16 sBh[128 * 40];
    __shared__ __align__(16) __nv_bfloat16 sBl[128 * 40];

    const int tid  = threadIdx.x;
    const int lane = tid & 31;
    const int wid  = tid >> 5;
    const int wm   = wid & 3;
    const int wn   = wid >> 2;
    const int bm   = blockIdx.y * 128;
    const int bn   = blockIdx.x * 128;
    const int z    = blockIdx.z;
    const int h    = z / ksplit;
    const int ks   = z - h * ksplit;
    const int klen = Kpad / ksplit;
    const int kb   = ks * klen;
    const int kValid = kValidA - kb;
    const int statsBase = h * NN_ + bm;

    float acc[2][8][4];
    #pragma unroll
    for (int i = 0; i < 2; i++)
        #pragma unroll
        for (int j = 0; j < 8; j++)
            #pragma unroll
            for (int q = 0; q < 4; q++) acc[i][j][q] = 0.f;

    const int npairs = (afp32 && A2f != nullptr) ? 2 : 1;

    for (int pr = 0; pr < npairs; ++pr) {
        const float* Af = nullptr;
        const __nv_bfloat16* Ahi = nullptr;
        const __nv_bfloat16* Alo = nullptr;
        if (afp32) {
            Af = (pr ? A2f : (const float*)A_) + h * zsA + kb;
        } else {
            Ahi = (const __nv_bfloat16*)A_  + h * zsA + kb;
            Alo = (const __nv_bfloat16*)Alo_ + h * zsA + kb;
        }
        const __nv_bfloat16* Bh = (pr ? B2h : B1h) + h * zsB + kb;
        const __nv_bfloat16* Bl = (pr ? B2l : B1l) + h * zsB + kb;

        uint4 stA[4], stB[4];

        auto prefetch = [&](int k0) {
            if (afp32) {
                #pragma unroll
                for (int i = 0; i < 4; i++) {
                    int l = tid + i * 256;
                    int r = l >> 3, g4 = l & 7;
                    float4 v = make_float4(0.f, 0.f, 0.f, 0.f);
                    if (k0 + g4 * 4 < kValid) {
                        v = *(const float4*)(Af + (size_t)(bm + r) * lda + k0 + g4 * 4);
                        if (rowstats) {
                            float2 st = rowstats[statsBase + r];
                            v.x = __expf(v.x - st.x) * st.y;
                            v.y = __expf(v.y - st.x) * st.y;
                            v.z = __expf(v.z - st.x) * st.y;
                            v.w = __expf(v.w - st.x) * st.y;
                        }
                    }
                    stA[i] = *(uint4*)&v;
                }
            } else {
                #pragma unroll
                for (int i = 0; i < 2; i++) {
                    int l = tid + i * 256;
                    int r = l >> 2, g = l & 3;
                    stA[i]     = *(const uint4*)(Ahi + (size_t)(bm + r) * lda + k0 + g * 8);
                    stA[i + 2] = *(const uint4*)(Alo + (size_t)(bm + r) * lda + k0 + g * 8);
                }
            }
            #pragma unroll
            for (int i = 0; i < 2; i++) {
                int l = tid + i * 256;
                int r = l >> 2, g = l & 3;
                if (bn + r < Nfull) {
                    stB[i]     = *(const uint4*)(Bh + (size_t)(bn + r) * ldb + k0 + g * 8);
                    stB[i + 2] = *(const uint4*)(Bl + (size_t)(bn + r) * ldb + k0 + g * 8);
                } else {
                    stB[i] = make_uint4(0, 0, 0, 0);
                    stB[i + 2] = make_uint4(0, 0, 0, 0);
                }
            }
        };

        auto store_smem = [&]() {
            if (afp32) {
                #pragma unroll
                for (int i = 0; i < 4; i++) {
                    int l = tid + i * 256;
                    int r = l >> 3, g4 = l & 7;
                    float4 v = *(float4*)&stA[i];
                    __nv_bfloat16 h0, l0, h1, l1, h2, l2, h3, l3;
                    splitf(v.x, h0, l0); splitf(v.y, h1, l1);
                    splitf(v.z, h2, l2); splitf(v.w, h3, l3);
                    __nv_bfloat162* ph = (__nv_bfloat162*)(sAh + r * 40 + g4 * 4);
                    __nv_bfloat162* pl = (__nv_bfloat162*)(sAl + r * 40 + g4 * 4);
                    __nv_bfloat162 t2;
                    t2.x = h0; t2.y = h1; ph[0] = t2;
                    t2.x = h2; t2.y = h3; ph[1] = t2;
                    t2.x = l0; t2.y = l1; pl[0] = t2;
                    t2.x = l2; t2.y = l3; pl[1] = t2;
                }
            } else {
                #pragma unroll
                for (int i = 0; i < 2; i++) {
                    int l = tid + i * 256;
                    int r = l >> 2, g = l & 3;
                    *(uint4*)(sAh + r * 40 + g * 8) = stA[i];
                    *(uint4*)(sAl + r * 40 + g * 8) = stA[i + 2];
                }
            }
            #pragma unroll
            for (int i = 0; i < 2; i++) {
                int l = tid + i * 256;
                int r = l >> 2, g = l & 3;
                *(uint4*)(sBh + r * 40 + g * 8) = stB[i];
                *(uint4*)(sBl + r * 40 + g * 8) = stB[i + 2];
            }
        };

        prefetch(0);
        for (int k0 = 0; k0 < klen; k0 += 32) {
            store_smem();
            __syncthreads();
            if (k0 + 32 < klen) prefetch(k0 + 32);

            #pragma unroll
            for (int ksf = 0; ksf < 2; ++ksf) {
                uint32_t ah[2][4], al[2][4];
                #pragma unroll
                for (int mt = 0; mt < 2; ++mt) {
                    int ar = wm * 32 + mt * 16 + (lane >> 2);
                    int off = ar * 40 + ksf * 16 + ((lane & 3) << 1);
                    ah[mt][0] = *(const uint32_t*)(sAh + off);
                    ah[mt][1] = *(const uint32_t*)(sAh + off + 8 * 40);
                    ah[mt][2] = *(const uint32_t*)(sAh + off + 8);
                    ah[mt][3] = *(const uint32_t*)(sAh + off + 8 * 40 + 8);
                    al[mt][0] = *(const uint32_t*)(sAl + off);
                    al[mt][1] = *(const uint32_t*)(sAl + off + 8 * 40);
                    al[mt][2] = *(const uint32_t*)(sAl + off + 8);
                    al[mt][3] = *(const uint32_t*)(sAl + off + 8 * 40 + 8);
                }
                #pragma unroll
                for (int nt = 0; nt < 8; ++nt) {
                    int br = wn * 64 + nt * 8 + (lane >> 2);
                    int off = br * 40 + ksf * 16 + ((lane & 3) << 1);
                    uint32_t bh[2], bl[2];
                    bh[0] = *(const uint32_t*)(sBh + off);
                    bh[1] = *(const uint32_t*)(sBh + off + 8);
                    bl[0] = *(const uint32_t*)(sBl + off);
                    bl[1] = *(const uint32_t*)(sBl + off + 8);
                    #pragma unroll
                    for (int mt = 0; mt < 2; ++mt) {
                        MMA_BF16(acc[mt][nt], ah[mt], bh);
                        MMA_BF16(acc[mt][nt], ah[mt], bl);
                        MMA_BF16(acc[mt][nt], al[mt], bh);
                    }
                }
            }
            __syncthreads();
        }
    }

    float* Cp = C + h * zsC;
    if (mode == 0) {
        #pragma unroll
        for (int mt = 0; mt < 2; ++mt) {
            int row = bm + wm * 32 + mt * 16 + (lane >> 2);
            #pragma unroll
            for (int nt = 0; nt < 8; ++nt) {
                int gc = bn + wn * 64 + nt * 8 + ((lane & 3) << 1);
                #pragma unroll
                for (int j = 0; j < 2; ++j) {
                    if (gc + j < Nfull) {
                        float bsv = bias ? bias[gc + j] : 0.f;
                        float v0 = alpha * acc[mt][nt][j] + bsv;
                        float v1 = alpha * acc[mt][nt][j + 2] + bsv;
                        if (relu) { v0 = fmaxf(v0, 0.f); v1 = fmaxf(v1, 0.f); }
                        Cp[(size_t)row * ldc + gc + j] = v0;
                        Cp[(size_t)(row + 8) * ldc + gc + j] = v1;
                    }
                }
            }
        }
    } else {
        int hofs = h * HD_;
        #pragma unroll
        for (int mt = 0; mt < 2; ++mt) {
            int row = bm + wm * 32 + mt * 16 + (lane >> 2);
            #pragma unroll
            for (int nt = 0; nt < 8; ++nt) {
                int gc = wn * 64 + nt * 8 + ((lane & 3) << 1);
                #pragma unroll
                for (int j = 0; j < 2; ++j) {
                    if (gc + j < Nfull) {
                        atomicAdd(&C[(size_t)row * ldc + hofs + gc + j], acc[mt][nt][j]);
                        atomicAdd(&C[(size_t)(row + 8) * ldc + hofs + gc + j], acc[mt][nt][j + 2]);
                    }
                }
            }
        }
    }
}

// ---------------- launch -----------------------------------------------------
extern "C" void kernel_launch(void* const* d_in, const int* in_sizes, int n_in,
                              void* d_out, int out_size) {
    const float* x        = (const float*)d_in[0];
    const int*   ei       = (const int*)d_in[1];
    const float* W1_self  = (const float*)d_in[2];
    const float* W1_neigh = (const float*)d_in[3];
    const float* b1       = (const float*)d_in[4];
    const float* W_in     = (const float*)d_in[5];
    const float* b_in     = (const float*)d_in[6];
    const float* W_out    = (const float*)d_in[7];
    const float* b_out    = (const float*)d_in[8];
    const float* W2_self  = (const float*)d_in[9];
    const float* W2_neigh = (const float*)d_in[10];
    const float* b2       = (const float*)d_in[11];
    const float* Wc       = (const float*)d_in[12];
    const float* bc       = (const float*)d_in[13];

    float* out_x      = (float*)d_out;
    float* out_logits = (float*)d_out + (size_t)NN_ * OUT_;

    int *degi;
    float *mean, *h1, *qkv, *scores, *attno, *h2, *tmp2;
    float2* stats;
    cudaGetSymbolAddress((void**)&degi,   g_degi);
    cudaGetSymbolAddress((void**)&mean,   g_mean);
    cudaGetSymbolAddress((void**)&h1,     g_h1);
    cudaGetSymbolAddress((void**)&qkv,    g_qkv);
    cudaGetSymbolAddress((void**)&scores, g_scores);
    cudaGetSymbolAddress((void**)&stats,  g_stats);
    cudaGetSymbolAddress((void**)&attno,  g_attno);
    cudaGetSymbolAddress((void**)&h2,     g_h2);
    cudaGetSymbolAddress((void**)&tmp2,   g_tmp2);

    __nv_bfloat16 *qh, *ql, *kh, *kl, *vth, *vtl;
    __nv_bfloat16 *w1sh, *w1sl, *w1nh, *w1nl, *winh, *winl, *woh, *wol;
    __nv_bfloat16 *w2sh, *w2sl, *w2nh, *w2nl, *wch, *wcl;
    cudaGetSymbolAddress((void**)&qh,   g_qh);
    cudaGetSymbolAddress((void**)&ql,   g_ql);
    cudaGetSymbolAddress((void**)&kh,   g_kh);
    cudaGetSymbolAddress((void**)&kl,   g_kl);
    cudaGetSymbolAddress((void**)&vth,  g_vth);
    cudaGetSymbolAddress((void**)&vtl,  g_vtl);
    cudaGetSymbolAddress((void**)&w1sh, g_w1sh); cudaGetSymbolAddress((void**)&w1sl, g_w1sl);
    cudaGetSymbolAddress((void**)&w1nh, g_w1nh); cudaGetSymbolAddress((void**)&w1nl, g_w1nl);
    cudaGetSymbolAddress((void**)&winh, g_winh); cudaGetSymbolAddress((void**)&winl, g_winl);
    cudaGetSymbolAddress((void**)&woh,  g_woh);  cudaGetSymbolAddress((void**)&wol,  g_wol);
    cudaGetSymbolAddress((void**)&w2sh, g_w2sh); cudaGetSymbolAddress((void**)&w2sl, g_w2sl);
    cudaGetSymbolAddress((void**)&w2nh, g_w2nh); cudaGetSymbolAddress((void**)&w2nl, g_w2nl);
    cudaGetSymbolAddress((void**)&wch,  g_wch);  cudaGetSymbolAddress((void**)&wcl,  g_wcl);

    const float scale = 1.0f / sqrtf((float)HD_);

    // ---- CSR build ----
    zero_i<<<16, 256>>>(degi, NN_);
    count_deg<<<EE_ / 256, 256>>>(ei);
    scan_offsets<<<1, 1024>>>();
    csr_fill<<<EE_ / 256, 256>>>(ei);

    // ---- weight pre-splits ----
    split_w<<<(HH_ * KP500 + 255) / 256, 256>>>(W1_self, HH_, IN_, KP500, w1sh, w1sl);
    split_w<<<(HH_ * KP500 + 255) / 256, 256>>>(W1_neigh, HH_, IN_, KP500, w1nh, w1nl);
    split_w<<<(3 * HH_ * KP500 + 255) / 256, 256>>>(W_in, 3 * HH_, HH_, KP500, winh, winl);
    split_w<<<(HH_ * KP500 + 255) / 256, 256>>>(W_out, HH_, HH_, KP500, woh, wol);
    split_w<<<(OUT_ * KP500 + 255) / 256, 256>>>(W2_self, OUT_, HH_, KP500, w2sh, w2sl);
    split_w<<<(OUT_ * KP500 + 255) / 256, 256>>>(W2_neigh, OUT_, HH_, KP500, w2nh, w2nl);
    split_w<<<(int)(((size_t)CC_ * 128 + 255) / 256), 256>>>(Wc, CC_, OUT_, 128, wch, wcl);

    // ---- SAGE 1 ----
    gather_mean<<<NN_, 128>>>(x, mean, IN_ / 4);
    {
        dim3 grid(4, 32, 1);
        gemm_mma_v2<<<grid, 256>>>(x, nullptr, mean, IN_,
                                   w1sh, w1sl, w1nh, w1nl, KP500,
                                   nullptr, b1, h1, HH_,
                                   HH_, KP500, IN_, 1.0f, 1, 1, 0,
                                   0, 0, 0, 1);
    }

    // ---- qkv projection ----
    {
        dim3 grid(12, 32, 1);
        gemm_mma_v2<<<grid, 256>>>(h1, nullptr, nullptr, HH_,
                                   winh, winl, nullptr, nullptr, KP500,
                                   nullptr, b_in, qkv, 3 * HH_,
                                   3 * HH_, KP500, HH_, 1.0f, 1, 0, 0,
                                   0, 0, 0, 1);
    }
    convert_qk_kernel<<<(NHEAD * NN_ * HDP_ + 255) / 256, 256>>>(qkv);
    convert_v_kernel<<<(NHEAD * HDP_ * NN_ + 255) / 256, 256>>>(qkv);

    // ---- QK^T (scaled) ----
    {
        dim3 grid(32, 32, NHEAD);
        gemm_mma_v2<<<grid, 256>>>(qh, ql, nullptr, HDP_,
                                   kh, kl, nullptr, nullptr, HDP_,
                                   nullptr, nullptr, scores, NN_,
                                   NN_, HDP_, HDP_, scale, 0, 0, 0,
                                   (size_t)NN_ * HDP_, (size_t)NN_ * HDP_,
                                   (size_t)NN_ * NN_, 1);
    }
    // ---- softmax stats ----
    stats_kernel<<<NHEAD * NN_, 256>>>(scores);

    // ---- PV with exp-on-load (split-K=4) ----
    zero_f<<<2048, 256>>>(attno, NN_ * HH_);
    {
        dim3 grid(1, 32, NHEAD * 4);
        gemm_mma_v2<<<grid, 256>>>(scores, nullptr, nullptr, NN_,
                                   vth, vtl, nullptr, nullptr, NN_,
                                   stats, nullptr, attno, HH_,
                                   HD_, NN_, NN_, 1.0f, 1, 0, 1,
                                   (size_t)NN_ * NN_, (size_t)HDP_ * NN_, 0, 4);
    }

    // ---- out projection ----
    {
        dim3 grid(4, 32, 1);
        gemm_mma_v2<<<grid, 256>>>(attno, nullptr, nullptr, HH_,
                                   woh, wol, nullptr, nullptr, KP500,
                                   nullptr, b_out, h2, HH_,
                                   HH_, KP500, HH_, 1.0f, 1, 1, 0,
                                   0, 0, 0, 1);
    }

    // ---- SAGE 2 (split-K=4 atomic, then bias+relu) ----
    gather_mean<<<NN_, 128>>>(h2, mean, HH_ / 4);
    zero_f<<<1600, 256>>>(tmp2, NN_ * OUT_);
    {
        dim3 grid(1, 32, 4);
        gemm_mma_v2<<<grid, 256>>>(h2, nullptr, mean, HH_,
                                   w2sh, w2sl, w2nh, w2nl, KP500,
                                   nullptr, nullptr, tmp2, OUT_,
                                   OUT_, KP500, HH_, 1.0f, 1, 0, 1,
                                   0, 0, 0, 4);
    }
    bias_relu_kernel<<<(NN_ * OUT_ + 255) / 256, 256>>>(tmp2, b2, out_x, NN_ * OUT_, OUT_);

    // ---- classifier ----
    {
        dim3 grid(CCP_ / 128, 32, 1);
        gemm_mma_v2<<<grid, 256>>>(out_x, nullptr, nullptr, OUT_,
                                   wch, wcl, nullptr, nullptr, 128,
                                   nullptr, bc, out_logits, CC_,
                                   CC_, 128, OUT_, 1.0f, 1, 0, 0,
                                   0, 0, 0, 1);
    }
}

// round 6
// speedup vs baseline: 4.8301x; 1.4153x over previous
#include <cuda_runtime.h>
#include <cuda_bf16.h>
#include <math.h>
#include <stdint.h>

#define NN_   4096
#define EE_   131072
#define IN_   500
#define HH_   500
#define OUT_  100
#define CC_   15451
#define CCP_  15488
#define NHEAD 4
#define HD_   125
#define HDP_  128
#define KP500 512
#define NKT   (NN_ / 64)   // 64 key tiles

// ---------------- scratch ----------------------------------------------------
__device__ int   g_degi[NN_];
__device__ int   g_off[NN_ + 1];
__device__ int   g_cur[NN_];
__device__ int   g_csr[EE_];
__device__ float g_mean[NN_ * HH_];
__device__ float g_h1[NN_ * HH_];
__device__ float g_qkv[NN_ * 3 * HH_];
__device__ float g_attno[NN_ * HH_];
__device__ float g_h2[NN_ * HH_];
__device__ float g_tmp2[NN_ * OUT_];

__device__ __nv_bfloat16 g_qh[NHEAD * NN_ * HDP_];
__device__ __nv_bfloat16 g_ql[NHEAD * NN_ * HDP_];
__device__ __nv_bfloat16 g_kh[NHEAD * NN_ * HDP_];
__device__ __nv_bfloat16 g_kl[NHEAD * NN_ * HDP_];
__device__ __nv_bfloat16 g_vth[NHEAD * HDP_ * NN_];
__device__ __nv_bfloat16 g_vtl[NHEAD * HDP_ * NN_];

__device__ __nv_bfloat16 g_w1sh[HH_ * KP500], g_w1sl[HH_ * KP500];
__device__ __nv_bfloat16 g_w1nh[HH_ * KP500], g_w1nl[HH_ * KP500];
__device__ __nv_bfloat16 g_winh[3 * HH_ * KP500], g_winl[3 * HH_ * KP500];
__device__ __nv_bfloat16 g_woh[HH_ * KP500], g_wol[HH_ * KP500];
__device__ __nv_bfloat16 g_w2sh[OUT_ * KP500], g_w2sl[OUT_ * KP500];
__device__ __nv_bfloat16 g_w2nh[OUT_ * KP500], g_w2nl[OUT_ * KP500];
__device__ __nv_bfloat16 g_wch[(size_t)CC_ * 128], g_wcl[(size_t)CC_ * 128];

// ---------------- helpers ----------------------------------------------------
__device__ __forceinline__ void splitf(float x, __nv_bfloat16& h, __nv_bfloat16& l) {
    h = __float2bfloat16(x);
    l = __float2bfloat16(x - __bfloat162float(h));
}
__device__ __forceinline__ void split2(float x, float y, uint32_t& hi, uint32_t& lo) {
    __nv_bfloat162 h2, l2;
    h2.x = __float2bfloat16(x);
    h2.y = __float2bfloat16(y);
    l2.x = __float2bfloat16(x - __bfloat162float(h2.x));
    l2.y = __float2bfloat16(y - __bfloat162float(h2.y));
    hi = *(uint32_t*)&h2;
    lo = *(uint32_t*)&l2;
}
__device__ __forceinline__ void cpasync16(void* sp, const void* gp) {
    uint32_t s = (uint32_t)__cvta_generic_to_shared(sp);
    asm volatile("cp.async.cg.shared.global [%0], [%1], 16;" :: "r"(s), "l"(gp));
}
#define CP_COMMIT() asm volatile("cp.async.commit_group;")
#define CP_WAIT(n)  asm volatile("cp.async.wait_group %0;" :: "n"(n))

#define MMA_BF16(d, a, b) \
  asm volatile("mma.sync.aligned.m16n8k16.row.col.f32.bf16.bf16.f32 " \
   "{%0,%1,%2,%3},{%4,%5,%6,%7},{%8,%9},{%0,%1,%2,%3};" \
   : "+f"((d)[0]), "+f"((d)[1]), "+f"((d)[2]), "+f"((d)[3]) \
   : "r"((a)[0]), "r"((a)[1]), "r"((a)[2]), "r"((a)[3]), "r"((b)[0]), "r"((b)[1]))

// ---------------- small kernels ----------------------------------------------
__global__ void zero_f(float* p, int n) {
    int i = blockIdx.x * blockDim.x + threadIdx.x;
    int stride = gridDim.x * blockDim.x;
    for (; i < n; i += stride) p[i] = 0.f;
}
__global__ void zero_i(int* p, int n) {
    int i = blockIdx.x * blockDim.x + threadIdx.x;
    if (i < n) p[i] = 0;
}
__global__ void count_deg(const int* __restrict__ ei) {
    int e = blockIdx.x * blockDim.x + threadIdx.x;
    if (e < EE_) atomicAdd(&g_degi[ei[EE_ + e]], 1);
}
__global__ __launch_bounds__(1024) void scan_offsets() {
    __shared__ int s[1024];
    int t = threadIdx.x;
    int base = t * 4;
    int lp[4];
    int sum = 0;
    #pragma unroll
    for (int i = 0; i < 4; i++) { int v = g_degi[base + i]; lp[i] = sum; sum += v; }
    s[t] = sum;
    __syncthreads();
    for (int off = 1; off < 1024; off <<= 1) {
        int x = (t >= off) ? s[t - off] : 0;
        __syncthreads();
        s[t] += x;
        __syncthreads();
    }
    int excl = (t > 0) ? s[t - 1] : 0;
    #pragma unroll
    for (int i = 0; i < 4; i++) {
        int o = excl + lp[i];
        g_off[base + i] = o;
        g_cur[base + i] = o;
    }
    if (t == 1023) g_off[NN_] = s[1023];
}
__global__ void csr_fill(const int* __restrict__ ei) {
    int e = blockIdx.x * blockDim.x + threadIdx.x;
    if (e >= EE_) return;
    int d = ei[EE_ + e];
    int pos = atomicAdd(&g_cur[d], 1);
    g_csr[pos] = ei[e];
}

__global__ __launch_bounds__(128) void gather_mean(const float* __restrict__ feat,
                                                   float* __restrict__ mean, int F4) {
    int node = blockIdx.x;
    int t = threadIdx.x;
    if (t >= F4) return;
    int beg = g_off[node], end = g_off[node + 1];
    const float4* f4 = (const float4*)feat;
    float4 acc = make_float4(0.f, 0.f, 0.f, 0.f);
    int e = beg;
    for (; e + 1 < end; e += 2) {
        int s0 = __ldg(&g_csr[e]);
        int s1 = __ldg(&g_csr[e + 1]);
        float4 v0 = f4[(size_t)s0 * F4 + t];
        float4 v1 = f4[(size_t)s1 * F4 + t];
        acc.x += v0.x; acc.y += v0.y; acc.z += v0.z; acc.w += v0.w;
        acc.x += v1.x; acc.y += v1.y; acc.z += v1.z; acc.w += v1.w;
    }
    if (e < end) {
        int s0 = __ldg(&g_csr[e]);
        float4 v0 = f4[(size_t)s0 * F4 + t];
        acc.x += v0.x; acc.y += v0.y; acc.z += v0.z; acc.w += v0.w;
    }
    float inv = 1.0f / fmaxf((float)(end - beg), 1.0f);
    ((float4*)mean)[(size_t)node * F4 + t] =
        make_float4(acc.x * inv, acc.y * inv, acc.z * inv, acc.w * inv);
}

__global__ void split_w(const float* __restrict__ W, int Nr, int Kr, int Kpad,
                        __nv_bfloat16* __restrict__ hi, __nv_bfloat16* __restrict__ lo) {
    long long idx = (long long)blockIdx.x * blockDim.x + threadIdx.x;
    long long total = (long long)Nr * Kpad;
    if (idx >= total) return;
    int k = (int)(idx % Kpad);
    long long n = idx / Kpad;
    float v = (k < Kr) ? W[n * Kr + k] : 0.f;
    splitf(v, hi[idx], lo[idx]);
}

__global__ void convert_qk_kernel(const float* __restrict__ qkv, float scale) {
    int idx = blockIdx.x * blockDim.x + threadIdx.x;
    if (idx >= NHEAD * NN_ * HDP_) return;
    int d = idx & 127;
    int n = (idx >> 7) & (NN_ - 1);
    int h = idx >> 19;
    float q = 0.f, k = 0.f;
    if (d < HD_) {
        const float* row = qkv + (size_t)n * (3 * HH_) + h * HD_ + d;
        q = row[0] * scale;
        k = row[HH_];
    }
    splitf(q, g_qh[idx], g_ql[idx]);
    splitf(k, g_kh[idx], g_kl[idx]);
}

__global__ void convert_v_kernel(const float* __restrict__ qkv) {
    int idx = blockIdx.x * blockDim.x + threadIdx.x;
    if (idx >= NHEAD * HDP_ * NN_) return;
    int n = idx & (NN_ - 1);
    int d = (idx >> 12) & 127;
    int h = idx >> 19;
    float v = 0.f;
    if (d < HD_) v = qkv[(size_t)n * (3 * HH_) + 2 * HH_ + h * HD_ + d];
    splitf(v, g_vth[idx], g_vtl[idx]);
}

__global__ void bias_relu_kernel(const float* __restrict__ in,
                                 const float* __restrict__ b,
                                 float* __restrict__ out, int n, int cols) {
    int i = blockIdx.x * blockDim.x + threadIdx.x;
    if (i >= n) return;
    out[i] = fmaxf(in[i] + b[i % cols], 0.f);
}

// ---------------- flash attention ---------------------------------------------
#define FQS (128 * 136)
#define FKS (64 * 136)
#define FVS (128 * 72)
#define FLASH_SMEM ((2 * FQS + 4 * FKS + 4 * FVS) * 2)

__global__ __launch_bounds__(256)
void flash_attn(const __nv_bfloat16* __restrict__ qh, const __nv_bfloat16* __restrict__ ql,
                const __nv_bfloat16* __restrict__ kh, const __nv_bfloat16* __restrict__ kl,
                const __nv_bfloat16* __restrict__ vth, const __nv_bfloat16* __restrict__ vtl,
                float* __restrict__ attno) {
    extern __shared__ __nv_bfloat16 sm[];
    __nv_bfloat16* sQh = sm;
    __nv_bfloat16* sQl = sm + FQS;
    __nv_bfloat16* sKb = sm + 2 * FQS;
    __nv_bfloat16* sVb = sm + 2 * FQS + 4 * FKS;

    const int tid  = threadIdx.x;
    const int lane = tid & 31;
    const int wid  = tid >> 5;
    const int g    = lane >> 2;
    const int c    = lane & 3;
    const int bm   = blockIdx.x * 128;
    const int h    = blockIdx.y;

    const __nv_bfloat16* qhp = qh + ((size_t)h * NN_ + bm) * HDP_;
    const __nv_bfloat16* qlp = ql + ((size_t)h * NN_ + bm) * HDP_;
    const __nv_bfloat16* khp = kh + (size_t)h * NN_ * HDP_;
    const __nv_bfloat16* klp = kl + (size_t)h * NN_ * HDP_;
    const __nv_bfloat16* vhp = vth + (size_t)h * HDP_ * NN_;
    const __nv_bfloat16* vlp = vtl + (size_t)h * HDP_ * NN_;

    #pragma unroll
    for (int i = 0; i < 16; i++) {
        int idx = tid + i * 256;
        int hf  = idx >> 11;
        int rem = idx & 2047;
        int row = rem >> 4;
        int ch  = rem & 15;
        const __nv_bfloat16* src = (hf ? qlp : qhp) + (size_t)row * HDP_ + ch * 8;
        cpasync16((hf ? sQl : sQh) + row * 136 + ch * 8, src);
    }

    auto kvload = [&](int j, int buf) {
        __nv_bfloat16* kb = sKb + buf * 2 * FKS;
        __nv_bfloat16* vb = sVb + buf * 2 * FVS;
        const int key0 = j * 64;
        #pragma unroll
        for (int i = 0; i < 8; i++) {
            int idx = tid + i * 256;
            int hf  = idx >> 10;
            int rem = idx & 1023;
            int row = rem >> 4;
            int ch  = rem & 15;
            const __nv_bfloat16* src = (hf ? klp : khp) + (size_t)(key0 + row) * HDP_ + ch * 8;
            cpasync16(kb + hf * FKS + row * 136 + ch * 8, src);
        }
        #pragma unroll
        for (int i = 0; i < 8; i++) {
            int idx = tid + i * 256;
            int hf  = idx >> 10;
            int rem = idx & 1023;
            int row = rem >> 3;
            int ch  = rem & 7;
            const __nv_bfloat16* src = (hf ? vlp : vhp) + (size_t)row * NN_ + key0 + ch * 8;
            cpasync16(vb + hf * FVS + row * 72 + ch * 8, src);
        }
    };

    kvload(0, 0);
    CP_COMMIT();

    float m0 = -1e30f, m1 = -1e30f, l0 = 0.f, l1 = 0.f;
    float acco[16][4];
    #pragma unroll
    for (int i = 0; i < 16; i++)
        #pragma unroll
        for (int q = 0; q < 4; q++) acco[i][q] = 0.f;

    const int arow = wid * 16 + g;

    for (int j = 0; j < NKT; ++j) {          // FIX: 64 tiles covering all 4096 keys
        if (j + 1 < NKT) {
            kvload(j + 1, (j + 1) & 1);
            CP_COMMIT();
            CP_WAIT(1);
        } else {
            CP_WAIT(0);
        }
        __syncthreads();

        const __nv_bfloat16* kbh = sKb + (j & 1) * 2 * FKS;
        const __nv_bfloat16* kbl = kbh + FKS;
        const __nv_bfloat16* vbh = sVb + (j & 1) * 2 * FVS;
        const __nv_bfloat16* vbl = vbh + FVS;

        float accs[8][4];
        #pragma unroll
        for (int i = 0; i < 8; i++)
            #pragma unroll
            for (int q = 0; q < 4; q++) accs[i][q] = 0.f;

        #pragma unroll
        for (int ks = 0; ks < 8; ++ks) {
            int ao = arow * 136 + ks * 16 + c * 2;
            uint32_t ahh[4], alo[4];
            ahh[0] = *(const uint32_t*)(sQh + ao);
            ahh[1] = *(const uint32_t*)(sQh + ao + 8 * 136);
            ahh[2] = *(const uint32_t*)(sQh + ao + 8);
            ahh[3] = *(const uint32_t*)(sQh + ao + 8 * 136 + 8);
            alo[0] = *(const uint32_t*)(sQl + ao);
            alo[1] = *(const uint32_t*)(sQl + ao + 8 * 136);
            alo[2] = *(const uint32_t*)(sQl + ao + 8);
            alo[3] = *(const uint32_t*)(sQl + ao + 8 * 136 + 8);
            #pragma unroll
            for (int nt = 0; nt < 8; ++nt) {
                int bo = (nt * 8 + g) * 136 + ks * 16 + c * 2;
                uint32_t bh[2], bl[2];
                bh[0] = *(const uint32_t*)(kbh + bo);
                bh[1] = *(const uint32_t*)(kbh + bo + 8);
                bl[0] = *(const uint32_t*)(kbl + bo);
                bl[1] = *(const uint32_t*)(kbl + bo + 8);
                MMA_BF16(accs[nt], ahh, bh);
                MMA_BF16(accs[nt], ahh, bl);
                MMA_BF16(accs[nt], alo, bh);
            }
        }

        float t0 = -1e30f, t1 = -1e30f;
        #pragma unroll
        for (int nt = 0; nt < 8; ++nt) {
            t0 = fmaxf(t0, fmaxf(accs[nt][0], accs[nt][1]));
            t1 = fmaxf(t1, fmaxf(accs[nt][2], accs[nt][3]));
        }
        t0 = fmaxf(t0, __shfl_xor_sync(0xffffffffu, t0, 1));
        t0 = fmaxf(t0, __shfl_xor_sync(0xffffffffu, t0, 2));
        t1 = fmaxf(t1, __shfl_xor_sync(0xffffffffu, t1, 1));
        t1 = fmaxf(t1, __shfl_xor_sync(0xffffffffu, t1, 2));
        float nm0 = fmaxf(m0, t0), nm1 = fmaxf(m1, t1);
        float sc0 = __expf(m0 - nm0), sc1 = __expf(m1 - nm1);

        uint32_t ph[4][4], pl[4][4];
        float ps0 = 0.f, ps1 = 0.f;
        #pragma unroll
        for (int kk = 0; kk < 4; ++kk) {
            float p00 = __expf(accs[2 * kk][0] - nm0);
            float p01 = __expf(accs[2 * kk][1] - nm0);
            float p02 = __expf(accs[2 * kk][2] - nm1);
            float p03 = __expf(accs[2 * kk][3] - nm1);
            float p10 = __expf(accs[2 * kk + 1][0] - nm0);
            float p11 = __expf(accs[2 * kk + 1][1] - nm0);
            float p12 = __expf(accs[2 * kk + 1][2] - nm1);
            float p13 = __expf(accs[2 * kk + 1][3] - nm1);
            ps0 += p00 + p01 + p10 + p11;
            ps1 += p02 + p03 + p12 + p13;
            split2(p00, p01, ph[kk][0], pl[kk][0]);
            split2(p02, p03, ph[kk][1], pl[kk][1]);
            split2(p10, p11, ph[kk][2], pl[kk][2]);
            split2(p12, p13, ph[kk][3], pl[kk][3]);
        }
        ps0 += __shfl_xor_sync(0xffffffffu, ps0, 1);
        ps0 += __shfl_xor_sync(0xffffffffu, ps0, 2);
        ps1 += __shfl_xor_sync(0xffffffffu, ps1, 1);
        ps1 += __shfl_xor_sync(0xffffffffu, ps1, 2);
        l0 = l0 * sc0 + ps0;
        l1 = l1 * sc1 + ps1;
        m0 = nm0;
        m1 = nm1;

        #pragma unroll
        for (int nt = 0; nt < 16; ++nt) {
            acco[nt][0] *= sc0; acco[nt][1] *= sc0;
            acco[nt][2] *= sc1; acco[nt][3] *= sc1;
        }

        #pragma unroll
        for (int nt = 0; nt < 16; ++nt) {
            #pragma unroll
            for (int kk = 0; kk < 4; ++kk) {
                int bo = (nt * 8 + g) * 72 + kk * 16 + c * 2;
                uint32_t bh[2], bl[2];
                bh[0] = *(const uint32_t*)(vbh + bo);
                bh[1] = *(const uint32_t*)(vbh + bo + 8);
                bl[0] = *(const uint32_t*)(vbl + bo);
                bl[1] = *(const uint32_t*)(vbl + bo + 8);
                MMA_BF16(acco[nt], ph[kk], bh);
                MMA_BF16(acco[nt], ph[kk], bl);
                MMA_BF16(acco[nt], pl[kk], bh);
            }
        }
        __syncthreads();
    }

    float i0 = 1.0f / l0, i1 = 1.0f / l1;
    int r0 = bm + arow;
    #pragma unroll
    for (int nt = 0; nt < 16; ++nt) {
        int col = nt * 8 + c * 2;
        if (col < HD_) {
            attno[(size_t)r0 * HH_ + h * HD_ + col]       = acco[nt][0] * i0;
            attno[(size_t)(r0 + 8) * HH_ + h * HD_ + col] = acco[nt][2] * i1;
        }
        if (col + 1 < HD_) {
            attno[(size_t)r0 * HH_ + h * HD_ + col + 1]       = acco[nt][1] * i0;
            attno[(size_t)(r0 + 8) * HH_ + h * HD_ + col + 1] = acco[nt][3] * i1;
        }
    }
}

// ---------------- unified bf16-split tensor-core GEMM (NT) --------------------
__global__ __launch_bounds__(256, 1)
void gemm_mma_v2(const void* __restrict__ A_, const void* __restrict__ Alo_,
                 const float* __restrict__ A2f, int lda,
                 const __nv_bfloat16* __restrict__ B1h, const __nv_bfloat16* __restrict__ B1l,
                 const __nv_bfloat16* __restrict__ B2h, const __nv_bfloat16* __restrict__ B2l,
                 int ldb,
                 const float* __restrict__ bias,
                 float* __restrict__ C, int ldc,
                 int Nfull, int Kpad, int kValidA, float alpha,
                 int afp32, int relu, int mode,
                 size_t zsA, size_t zsB, size_t zsC, int ksplit) {
    __shared__ __align__(16) __nv_bfloat16 sAh[128 * 40];
    __shared__ __align__(16) __nv_bfloat16 sAl[128 * 40];
    __shared__ __align__(16) __nv_bfloat16 sBh[128 * 40];
    __shared__ __align__(16) __nv_bfloat16 sBl[128 * 40];

    const int tid  = threadIdx.x;
    const int lane = tid & 31;
    const int wid  = tid >> 5;
    const int wm   = wid & 3;
    const int wn   = wid >> 2;
    const int bm   = blockIdx.y * 128;
    const int bn   = blockIdx.x * 128;
    const int z    = blockIdx.z;
    const int h    = z / ksplit;
    const int ks   = z - h * ksplit;
    const int klen = Kpad / ksplit;
    const int kb   = ks * klen;
    const int kValid = kValidA - kb;

    float acc[2][8][4];
    #pragma unroll
    for (int i = 0; i < 2; i++)
        #pragma unroll
        for (int j = 0; j < 8; j++)
            #pragma unroll
            for (int q = 0; q < 4; q++) acc[i][j][q] = 0.f;

    const int npairs = (afp32 && A2f != nullptr) ? 2 : 1;

    for (int pr = 0; pr < npairs; ++pr) {
        const float* Af = nullptr;
        const __nv_bfloat16* Ahi = nullptr;
        const __nv_bfloat16* Alo = nullptr;
        if (afp32) {
            Af = (pr ? A2f : (const float*)A_) + h * zsA + kb;
        } else {
            Ahi = (const __nv_bfloat16*)A_  + h * zsA + kb;
            Alo = (const __nv_bfloat16*)Alo_ + h * zsA + kb;
        }
        const __nv_bfloat16* Bh = (pr ? B2h : B1h) + h * zsB + kb;
        const __nv_bfloat16* Bl = (pr ? B2l : B1l) + h * zsB + kb;

        uint4 stA[4], stB[4];

        auto prefetch = [&](int k0) {
            if (afp32) {
                #pragma unroll
                for (int i = 0; i < 4; i++) {
                    int l = tid + i * 256;
                    int r = l >> 3, g4 = l & 7;
                    float4 v = make_float4(0.f, 0.f, 0.f, 0.f);
                    if (k0 + g4 * 4 < kValid)
                        v = *(const float4*)(Af + (size_t)(bm + r) * lda + k0 + g4 * 4);
                    stA[i] = *(uint4*)&v;
                }
            } else {
                #pragma unroll
                for (int i = 0; i < 2; i++) {
                    int l = tid + i * 256;
                    int r = l >> 2, g = l & 3;
                    stA[i]     = *(const uint4*)(Ahi + (size_t)(bm + r) * lda + k0 + g * 8);
                    stA[i + 2] = *(const uint4*)(Alo + (size_t)(bm + r) * lda + k0 + g * 8);
                }
            }
            #pragma unroll
            for (int i = 0; i < 2; i++) {
                int l = tid + i * 256;
                int r = l >> 2, g = l & 3;
                if (bn + r < Nfull) {
                    stB[i]     = *(const uint4*)(Bh + (size_t)(bn + r) * ldb + k0 + g * 8);
                    stB[i + 2] = *(const uint4*)(Bl + (size_t)(bn + r) * ldb + k0 + g * 8);
                } else {
                    stB[i] = make_uint4(0, 0, 0, 0);
                    stB[i + 2] = make_uint4(0, 0, 0, 0);
                }
            }
        };

        auto store_smem = [&]() {
            if (afp32) {
                #pragma unroll
                for (int i = 0; i < 4; i++) {
                    int l = tid + i * 256;
                    int r = l >> 3, g4 = l & 7;
                    float4 v = *(float4*)&stA[i];
                    __nv_bfloat16 h0, l0, h1, l1, h2, l2, h3, l3;
                    splitf(v.x, h0, l0); splitf(v.y, h1, l1);
                    splitf(v.z, h2, l2); splitf(v.w, h3, l3);
                    __nv_bfloat162* pph = (__nv_bfloat162*)(sAh + r * 40 + g4 * 4);
                    __nv_bfloat162* ppl = (__nv_bfloat162*)(sAl + r * 40 + g4 * 4);
                    __nv_bfloat162 t2;
                    t2.x = h0; t2.y = h1; pph[0] = t2;
                    t2.x = h2; t2.y = h3; pph[1] = t2;
                    t2.x = l0; t2.y = l1; ppl[0] = t2;
                    t2.x = l2; t2.y = l3; ppl[1] = t2;
                }
            } else {
                #pragma unroll
                for (int i = 0; i < 2; i++) {
                    int l = tid + i * 256;
                    int r = l >> 2, g = l & 3;
                    *(uint4*)(sAh + r * 40 + g * 8) = stA[i];
                    *(uint4*)(sAl + r * 40 + g * 8) = stA[i + 2];
                }
            }
            #pragma unroll
            for (int i = 0; i < 2; i++) {
                int l = tid + i * 256;
                int r = l >> 2, g = l & 3;
                *(uint4*)(sBh + r * 40 + g * 8) = stB[i];
                *(uint4*)(sBl + r * 40 + g * 8) = stB[i + 2];
            }
        };

        prefetch(0);
        for (int k0 = 0; k0 < klen; k0 += 32) {
            store_smem();
            __syncthreads();
            if (k0 + 32 < klen) prefetch(k0 + 32);

            #pragma unroll
            for (int ksf = 0; ksf < 2; ++ksf) {
                uint32_t ah[2][4], al[2][4];
                #pragma unroll
                for (int mt = 0; mt < 2; ++mt) {
                    int ar = wm * 32 + mt * 16 + (lane >> 2);
                    int off = ar * 40 + ksf * 16 + ((lane & 3) << 1);
                    ah[mt][0] = *(const uint32_t*)(sAh + off);
                    ah[mt][1] = *(const uint32_t*)(sAh + off + 8 * 40);
                    ah[mt][2] = *(const uint32_t*)(sAh + off + 8);
                    ah[mt][3] = *(const uint32_t*)(sAh + off + 8 * 40 + 8);
                    al[mt][0] = *(const uint32_t*)(sAl + off);
                    al[mt][1] = *(const uint32_t*)(sAl + off + 8 * 40);
                    al[mt][2] = *(const uint32_t*)(sAl + off + 8);
                    al[mt][3] = *(const uint32_t*)(sAl + off + 8 * 40 + 8);
                }
                #pragma unroll
                for (int nt = 0; nt < 8; ++nt) {
                    int br = wn * 64 + nt * 8 + (lane >> 2);
                    int off = br * 40 + ksf * 16 + ((lane & 3) << 1);
                    uint32_t bh[2], bl[2];
                    bh[0] = *(const uint32_t*)(sBh + off);
                    bh[1] = *(const uint32_t*)(sBh + off + 8);
                    bl[0] = *(const uint32_t*)(sBl + off);
                    bl[1] = *(const uint32_t*)(sBl + off + 8);
                    #pragma unroll
                    for (int mt = 0; mt < 2; ++mt) {
                        MMA_BF16(acc[mt][nt], ah[mt], bh);
                        MMA_BF16(acc[mt][nt], ah[mt], bl);
                        MMA_BF16(acc[mt][nt], al[mt], bh);
                    }
                }
            }
            __syncthreads();
        }
    }

    float* Cp = C + h * zsC;
    if (mode == 0) {
        #pragma unroll
        for (int mt = 0; mt < 2; ++mt) {
            int row = bm + wm * 32 + mt * 16 + (lane >> 2);
            #pragma unroll
            for (int nt = 0; nt < 8; ++nt) {
                int gc = bn + wn * 64 + nt * 8 + ((lane & 3) << 1);
                #pragma unroll
                for (int j = 0; j < 2; ++j) {
                    if (gc + j < Nfull) {
                        float bsv = bias ? bias[gc + j] : 0.f;
                        float v0 = alpha * acc[mt][nt][j] + bsv;
                        float v1 = alpha * acc[mt][nt][j + 2] + bsv;
                        if (relu) { v0 = fmaxf(v0, 0.f); v1 = fmaxf(v1, 0.f); }
                        Cp[(size_t)row * ldc + gc + j] = v0;
                        Cp[(size_t)(row + 8) * ldc + gc + j] = v1;
                    }
                }
            }
        }
    } else {
        int hofs = h * HD_;
        #pragma unroll
        for (int mt = 0; mt < 2; ++mt) {
            int row = bm + wm * 32 + mt * 16 + (lane >> 2);
            #pragma unroll
            for (int nt = 0; nt < 8; ++nt) {
                int gc = wn * 64 + nt * 8 + ((lane & 3) << 1);
                #pragma unroll
                for (int j = 0; j < 2; ++j) {
                    if (gc + j < Nfull) {
                        atomicAdd(&C[(size_t)row * ldc + hofs + gc + j], acc[mt][nt][j]);
                        atomicAdd(&C[(size_t)(row + 8) * ldc + hofs + gc + j], acc[mt][nt][j + 2]);
                    }
                }
            }
        }
    }
}

// ---------------- launch -----------------------------------------------------
extern "C" void kernel_launch(void* const* d_in, const int* in_sizes, int n_in,
                              void* d_out, int out_size) {
    const float* x        = (const float*)d_in[0];
    const int*   ei       = (const int*)d_in[1];
    const float* W1_self  = (const float*)d_in[2];
    const float* W1_neigh = (const float*)d_in[3];
    const float* b1       = (const float*)d_in[4];
    const float* W_in     = (const float*)d_in[5];
    const float* b_in     = (const float*)d_in[6];
    const float* W_out    = (const float*)d_in[7];
    const float* b_out    = (const float*)d_in[8];
    const float* W2_self  = (const float*)d_in[9];
    const float* W2_neigh = (const float*)d_in[10];
    const float* b2       = (const float*)d_in[11];
    const float* Wc       = (const float*)d_in[12];
    const float* bc       = (const float*)d_in[13];

    float* out_x      = (float*)d_out;
    float* out_logits = (float*)d_out + (size_t)NN_ * OUT_;

    int* degi;
    float *mean, *h1, *qkv, *attno, *h2, *tmp2;
    cudaGetSymbolAddress((void**)&degi,  g_degi);
    cudaGetSymbolAddress((void**)&mean,  g_mean);
    cudaGetSymbolAddress((void**)&h1,    g_h1);
    cudaGetSymbolAddress((void**)&qkv,   g_qkv);
    cudaGetSymbolAddress((void**)&attno, g_attno);
    cudaGetSymbolAddress((void**)&h2,    g_h2);
    cudaGetSymbolAddress((void**)&tmp2,  g_tmp2);

    __nv_bfloat16 *qh, *ql, *kh, *kl, *vth, *vtl;
    __nv_bfloat16 *w1sh, *w1sl, *w1nh, *w1nl, *winh, *winl, *woh, *wol;
    __nv_bfloat16 *w2sh, *w2sl, *w2nh, *w2nl, *wch, *wcl;
    cudaGetSymbolAddress((void**)&qh,   g_qh);
    cudaGetSymbolAddress((void**)&ql,   g_ql);
    cudaGetSymbolAddress((void**)&kh,   g_kh);
    cudaGetSymbolAddress((void**)&kl,   g_kl);
    cudaGetSymbolAddress((void**)&vth,  g_vth);
    cudaGetSymbolAddress((void**)&vtl,  g_vtl);
    cudaGetSymbolAddress((void**)&w1sh, g_w1sh); cudaGetSymbolAddress((void**)&w1sl, g_w1sl);
    cudaGetSymbolAddress((void**)&w1nh, g_w1nh); cudaGetSymbolAddress((void**)&w1nl, g_w1nl);
    cudaGetSymbolAddress((void**)&winh, g_winh); cudaGetSymbolAddress((void**)&winl, g_winl);
    cudaGetSymbolAddress((void**)&woh,  g_woh);  cudaGetSymbolAddress((void**)&wol,  g_wol);
    cudaGetSymbolAddress((void**)&w2sh, g_w2sh); cudaGetSymbolAddress((void**)&w2sl, g_w2sl);
    cudaGetSymbolAddress((void**)&w2nh, g_w2nh); cudaGetSymbolAddress((void**)&w2nl, g_w2nl);
    cudaGetSymbolAddress((void**)&wch,  g_wch);  cudaGetSymbolAddress((void**)&wcl,  g_wcl);

    cudaFuncSetAttribute(flash_attn, cudaFuncAttributeMaxDynamicSharedMemorySize, FLASH_SMEM);

    const float scale = 1.0f / sqrtf((float)HD_);

    // ---- CSR build ----
    zero_i<<<16, 256>>>(degi, NN_);
    count_deg<<<EE_ / 256, 256>>>(ei);
    scan_offsets<<<1, 1024>>>();
    csr_fill<<<EE_ / 256, 256>>>(ei);

    // ---- weight pre-splits ----
    split_w<<<(HH_ * KP500 + 255) / 256, 256>>>(W1_self, HH_, IN_, KP500, w1sh, w1sl);
    split_w<<<(HH_ * KP500 + 255) / 256, 256>>>(W1_neigh, HH_, IN_, KP500, w1nh, w1nl);
    split_w<<<(3 * HH_ * KP500 + 255) / 256, 256>>>(W_in, 3 * HH_, HH_, KP500, winh, winl);
    split_w<<<(HH_ * KP500 + 255) / 256, 256>>>(W_out, HH_, HH_, KP500, woh, wol);
    split_w<<<(OUT_ * KP500 + 255) / 256, 256>>>(W2_self, OUT_, HH_, KP500, w2sh, w2sl);
    split_w<<<(OUT_ * KP500 + 255) / 256, 256>>>(W2_neigh, OUT_, HH_, KP500, w2nh, w2nl);
    split_w<<<(int)(((size_t)CC_ * 128 + 255) / 256), 256>>>(Wc, CC_, OUT_, 128, wch, wcl);

    // ---- SAGE 1 ----
    gather_mean<<<NN_, 128>>>(x, mean, IN_ / 4);
    {
        dim3 grid(4, 32, 1);
        gemm_mma_v2<<<grid, 256>>>(x, nullptr, mean, IN_,
                                   w1sh, w1sl, w1nh, w1nl, KP500,
                                   b1, h1, HH_,
                                   HH_, KP500, IN_, 1.0f, 1, 1, 0,
                                   0, 0, 0, 1);
    }

    // ---- qkv projection ----
    {
        dim3 grid(12, 32, 1);
        gemm_mma_v2<<<grid, 256>>>(h1, nullptr, nullptr, HH_,
                                   winh, winl, nullptr, nullptr, KP500,
                                   b_in, qkv, 3 * HH_,
                                   3 * HH_, KP500, HH_, 1.0f, 1, 0, 0,
                                   0, 0, 0, 1);
    }
    convert_qk_kernel<<<(NHEAD * NN_ * HDP_ + 255) / 256, 256>>>(qkv, scale);
    convert_v_kernel<<<(NHEAD * HDP_ * NN_ + 255) / 256, 256>>>(qkv);

    // ---- fused flash attention ----
    {
        dim3 grid(NN_ / 128, NHEAD);
        flash_attn<<<grid, 256, FLASH_SMEM>>>(qh, ql, kh, kl, vth, vtl, attno);
    }

    // ---- out projection ----
    {
        dim3 grid(4, 32, 1);
        gemm_mma_v2<<<grid, 256>>>(attno, nullptr, nullptr, HH_,
                                   woh, wol, nullptr, nullptr, KP500,
                                   b_out, h2, HH_,
                                   HH_, KP500, HH_, 1.0f, 1, 1, 0,
                                   0, 0, 0, 1);
    }

    // ---- SAGE 2 (split-K=4 atomic, then bias+relu) ----
    gather_mean<<<NN_, 128>>>(h2, mean, HH_ / 4);
    zero_f<<<1600, 256>>>(tmp2, NN_ * OUT_);
    {
        dim3 grid(1, 32, 4);
        gemm_mma_v2<<<grid, 256>>>(h2, nullptr, mean, HH_,
                                   w2sh, w2sl, w2nh, w2nl, KP500,
                                   nullptr, tmp2, OUT_,
                                   OUT_, KP500, HH_, 1.0f, 1, 0, 1,
                                   0, 0, 0, 4);
    }
    bias_relu_kernel<<<(NN_ * OUT_ + 255) / 256, 256>>>(tmp2, b2, out_x, NN_ * OUT_, OUT_);

    // ---- classifier ----
    {
        dim3 grid(CCP_ / 128, 32, 1);
        gemm_mma_v2<<<grid, 256>>>(out_x, nullptr, nullptr, OUT_,
                                   wch, wcl, nullptr, nullptr, 128,
                                   bc, out_logits, CC_,
                                   CC_, 128, OUT_, 1.0f, 1, 0, 0,
                                   0, 0, 0, 1);
    }
}

// round 7
// speedup vs baseline: 5.5034x; 1.1394x over previous
#include <cuda_runtime.h>
#include <cuda_bf16.h>
#include <math.h>
#include <stdint.h>

#define NN_   4096
#define EE_   131072
#define IN_   500
#define HH_   500
#define OUT_  100
#define CC_   15451
#define CCP_  15488
#define NHEAD 4
#define HD_   125
#define HDP_  128
#define KP500 512
#define NKT   (NN_ / 64)

// ---------------- scratch ----------------------------------------------------
__device__ int   g_degi[NN_];
__device__ int   g_off[NN_ + 1];
__device__ int   g_cur[NN_];
__device__ int   g_csr[EE_];
__device__ float g_mean[NN_ * HH_];
__device__ float g_h1[NN_ * HH_];
__device__ float g_qkv[NN_ * 3 * HH_];
__device__ float g_attno[NN_ * HH_];
__device__ float g_h2[NN_ * HH_];
__device__ float g_tmp2[NN_ * OUT_];

__device__ __nv_bfloat16 g_qh[NHEAD * NN_ * HDP_];
__device__ __nv_bfloat16 g_ql[NHEAD * NN_ * HDP_];
__device__ __nv_bfloat16 g_kh[NHEAD * NN_ * HDP_];
__device__ __nv_bfloat16 g_kl[NHEAD * NN_ * HDP_];
__device__ __nv_bfloat16 g_vth[NHEAD * HDP_ * NN_];
__device__ __nv_bfloat16 g_vtl[NHEAD * HDP_ * NN_];

__device__ __nv_bfloat16 g_w1sh[HH_ * KP500], g_w1sl[HH_ * KP500];
__device__ __nv_bfloat16 g_w1nh[HH_ * KP500], g_w1nl[HH_ * KP500];
__device__ __nv_bfloat16 g_winh[3 * HH_ * KP500], g_winl[3 * HH_ * KP500];
__device__ __nv_bfloat16 g_woh[HH_ * KP500], g_wol[HH_ * KP500];
__device__ __nv_bfloat16 g_w2sh[OUT_ * KP500], g_w2sl[OUT_ * KP500];
__device__ __nv_bfloat16 g_w2nh[OUT_ * KP500], g_w2nl[OUT_ * KP500];
__device__ __nv_bfloat16 g_wch[(size_t)CC_ * 128], g_wcl[(size_t)CC_ * 128];

// ---------------- helpers ----------------------------------------------------
__device__ __forceinline__ void splitf(float x, __nv_bfloat16& h, __nv_bfloat16& l) {
    h = __float2bfloat16(x);
    l = __float2bfloat16(x - __bfloat162float(h));
}
__device__ __forceinline__ void split2(float x, float y, uint32_t& hi, uint32_t& lo) {
    __nv_bfloat162 h2, l2;
    h2.x = __float2bfloat16(x);
    h2.y = __float2bfloat16(y);
    l2.x = __float2bfloat16(x - __bfloat162float(h2.x));
    l2.y = __float2bfloat16(y - __bfloat162float(h2.y));
    hi = *(uint32_t*)&h2;
    lo = *(uint32_t*)&l2;
}
__device__ __forceinline__ void cpasync16(void* sp, const void* gp) {
    uint32_t s = (uint32_t)__cvta_generic_to_shared(sp);
    asm volatile("cp.async.cg.shared.global [%0], [%1], 16;" :: "r"(s), "l"(gp));
}
#define CP_COMMIT() asm volatile("cp.async.commit_group;")
#define CP_WAIT(n)  asm volatile("cp.async.wait_group %0;" :: "n"(n))

#define MMA_BF16(d, a, b) \
  asm volatile("mma.sync.aligned.m16n8k16.row.col.f32.bf16.bf16.f32 " \
   "{%0,%1,%2,%3},{%4,%5,%6,%7},{%8,%9},{%0,%1,%2,%3};" \
   : "+f"((d)[0]), "+f"((d)[1]), "+f"((d)[2]), "+f"((d)[3]) \
   : "r"((a)[0]), "r"((a)[1]), "r"((a)[2]), "r"((a)[3]), "r"((b)[0]), "r"((b)[1]))

// ldmatrix A-fragment (m16k16): matrices = [r0-7,k0-7][r8-15,k0-7][r0-7,k8-15][r8-15,k8-15]
__device__ __forceinline__ void ldmA(uint32_t* r, const __nv_bfloat16* base, int S) {
    int l = threadIdx.x & 31;
    const __nv_bfloat16* p = (l < 16) ? (base + l * S) : (base + (l - 16) * S + 8);
    uint32_t a = (uint32_t)__cvta_generic_to_shared(p);
    asm volatile("ldmatrix.sync.aligned.m8n8.x4.shared.b16 {%0,%1,%2,%3}, [%4];"
                 : "=r"(r[0]), "=r"(r[1]), "=r"(r[2]), "=r"(r[3]) : "r"(a));
}
// ldmatrix B double fragment (n16k16 -> two n8k16 frags):
// r0,r1 = frag(rows0-7){b0,b1}; r2,r3 = frag(rows8-15){b0,b1}
__device__ __forceinline__ void ldmB(uint32_t* r, const __nv_bfloat16* base, int S) {
    int l = threadIdx.x & 31;
    int q = l >> 3, rr = l & 7;
    const __nv_bfloat16* p = base + (rr + ((q >> 1) << 3)) * S + ((q & 1) << 3);
    uint32_t a = (uint32_t)__cvta_generic_to_shared(p);
    asm volatile("ldmatrix.sync.aligned.m8n8.x4.shared.b16 {%0,%1,%2,%3}, [%4];"
                 : "=r"(r[0]), "=r"(r[1]), "=r"(r[2]), "=r"(r[3]) : "r"(a));
}

// ---------------- small kernels ----------------------------------------------
__global__ void zero_f(float* p, int n) {
    int i = blockIdx.x * blockDim.x + threadIdx.x;
    int stride = gridDim.x * blockDim.x;
    for (; i < n; i += stride) p[i] = 0.f;
}
__global__ void zero_i(int* p, int n) {
    int i = blockIdx.x * blockDim.x + threadIdx.x;
    if (i < n) p[i] = 0;
}
__global__ void count_deg(const int* __restrict__ ei) {
    int e = blockIdx.x * blockDim.x + threadIdx.x;
    if (e < EE_) atomicAdd(&g_degi[ei[EE_ + e]], 1);
}
__global__ __launch_bounds__(1024) void scan_offsets() {
    __shared__ int s[1024];
    int t = threadIdx.x;
    int base = t * 4;
    int lp[4];
    int sum = 0;
    #pragma unroll
    for (int i = 0; i < 4; i++) { int v = g_degi[base + i]; lp[i] = sum; sum += v; }
    s[t] = sum;
    __syncthreads();
    for (int off = 1; off < 1024; off <<= 1) {
        int x = (t >= off) ? s[t - off] : 0;
        __syncthreads();
        s[t] += x;
        __syncthreads();
    }
    int excl = (t > 0) ? s[t - 1] : 0;
    #pragma unroll
    for (int i = 0; i < 4; i++) {
        int o = excl + lp[i];
        g_off[base + i] = o;
        g_cur[base + i] = o;
    }
    if (t == 1023) g_off[NN_] = s[1023];
}
__global__ void csr_fill(const int* __restrict__ ei) {
    int e = blockIdx.x * blockDim.x + threadIdx.x;
    if (e >= EE_) return;
    int d = ei[EE_ + e];
    int pos = atomicAdd(&g_cur[d], 1);
    g_csr[pos] = ei[e];
}

__global__ __launch_bounds__(128) void gather_mean(const float* __restrict__ feat,
                                                   float* __restrict__ mean, int F4) {
    int node = blockIdx.x;
    int t = threadIdx.x;
    if (t >= F4) return;
    int beg = g_off[node], end = g_off[node + 1];
    const float4* f4 = (const float4*)feat;
    float4 acc = make_float4(0.f, 0.f, 0.f, 0.f);
    int e = beg;
    for (; e + 1 < end; e += 2) {
        int s0 = __ldg(&g_csr[e]);
        int s1 = __ldg(&g_csr[e + 1]);
        float4 v0 = f4[(size_t)s0 * F4 + t];
        float4 v1 = f4[(size_t)s1 * F4 + t];
        acc.x += v0.x; acc.y += v0.y; acc.z += v0.z; acc.w += v0.w;
        acc.x += v1.x; acc.y += v1.y; acc.z += v1.z; acc.w += v1.w;
    }
    if (e < end) {
        int s0 = __ldg(&g_csr[e]);
        float4 v0 = f4[(size_t)s0 * F4 + t];
        acc.x += v0.x; acc.y += v0.y; acc.z += v0.z; acc.w += v0.w;
    }
    float inv = 1.0f / fmaxf((float)(end - beg), 1.0f);
    ((float4*)mean)[(size_t)node * F4 + t] =
        make_float4(acc.x * inv, acc.y * inv, acc.z * inv, acc.w * inv);
}

__global__ void split_w(const float* __restrict__ W, int Nr, int Kr, int Kpad,
                        __nv_bfloat16* __restrict__ hi, __nv_bfloat16* __restrict__ lo) {
    long long idx = (long long)blockIdx.x * blockDim.x + threadIdx.x;
    long long total = (long long)Nr * Kpad;
    if (idx >= total) return;
    int k = (int)(idx % Kpad);
    long long n = idx / Kpad;
    float v = (k < Kr) ? W[n * Kr + k] : 0.f;
    splitf(v, hi[idx], lo[idx]);
}

__global__ void convert_qk_kernel(const float* __restrict__ qkv, float scale) {
    int idx = blockIdx.x * blockDim.x + threadIdx.x;
    if (idx >= NHEAD * NN_ * HDP_) return;
    int d = idx & 127;
    int n = (idx >> 7) & (NN_ - 1);
    int h = idx >> 19;
    float q = 0.f, k = 0.f;
    if (d < HD_) {
        const float* row = qkv + (size_t)n * (3 * HH_) + h * HD_ + d;
        q = row[0] * scale;
        k = row[HH_];
    }
    splitf(q, g_qh[idx], g_ql[idx]);
    splitf(k, g_kh[idx], g_kl[idx]);
}

__global__ void convert_v_kernel(const float* __restrict__ qkv) {
    int idx = blockIdx.x * blockDim.x + threadIdx.x;
    if (idx >= NHEAD * HDP_ * NN_) return;
    int n = idx & (NN_ - 1);
    int d = (idx >> 12) & 127;
    int h = idx >> 19;
    float v = 0.f;
    if (d < HD_) v = qkv[(size_t)n * (3 * HH_) + 2 * HH_ + h * HD_ + d];
    splitf(v, g_vth[idx], g_vtl[idx]);
}

__global__ void bias_relu_kernel(const float* __restrict__ in,
                                 const float* __restrict__ b,
                                 float* __restrict__ out, int n, int cols) {
    int i = blockIdx.x * blockDim.x + threadIdx.x;
    if (i >= n) return;
    out[i] = fmaxf(in[i] + b[i % cols], 0.f);
}

// ---------------- flash attention ---------------------------------------------
#define FQS (128 * 136)
#define FKS (64 * 136)
#define FVS (128 * 72)
#define FLASH_SMEM ((2 * FQS + 4 * FKS + 4 * FVS) * 2)

__global__ __launch_bounds__(256)
void flash_attn(const __nv_bfloat16* __restrict__ qh, const __nv_bfloat16* __restrict__ ql,
                const __nv_bfloat16* __restrict__ kh, const __nv_bfloat16* __restrict__ kl,
                const __nv_bfloat16* __restrict__ vth, const __nv_bfloat16* __restrict__ vtl,
                float* __restrict__ attno) {
    extern __shared__ __nv_bfloat16 sm[];
    __nv_bfloat16* sQh = sm;
    __nv_bfloat16* sQl = sm + FQS;
    __nv_bfloat16* sKb = sm + 2 * FQS;
    __nv_bfloat16* sVb = sm + 2 * FQS + 4 * FKS;

    const int tid  = threadIdx.x;
    const int lane = tid & 31;
    const int wid  = tid >> 5;
    const int g    = lane >> 2;
    const int c    = lane & 3;
    const int bm   = blockIdx.x * 128;
    const int h    = blockIdx.y;

    const __nv_bfloat16* qhp = qh + ((size_t)h * NN_ + bm) * HDP_;
    const __nv_bfloat16* qlp = ql + ((size_t)h * NN_ + bm) * HDP_;
    const __nv_bfloat16* khp = kh + (size_t)h * NN_ * HDP_;
    const __nv_bfloat16* klp = kl + (size_t)h * NN_ * HDP_;
    const __nv_bfloat16* vhp = vth + (size_t)h * HDP_ * NN_;
    const __nv_bfloat16* vlp = vtl + (size_t)h * HDP_ * NN_;

    #pragma unroll
    for (int i = 0; i < 16; i++) {
        int idx = tid + i * 256;
        int hf  = idx >> 11;
        int rem = idx & 2047;
        int row = rem >> 4;
        int ch  = rem & 15;
        const __nv_bfloat16* src = (hf ? qlp : qhp) + (size_t)row * HDP_ + ch * 8;
        cpasync16((hf ? sQl : sQh) + row * 136 + ch * 8, src);
    }

    auto kvload = [&](int j, int buf) {
        __nv_bfloat16* kb = sKb + buf * 2 * FKS;
        __nv_bfloat16* vb = sVb + buf * 2 * FVS;
        const int key0 = j * 64;
        #pragma unroll
        for (int i = 0; i < 8; i++) {
            int idx = tid + i * 256;
            int hf  = idx >> 10;
            int rem = idx & 1023;
            int row = rem >> 4;
            int ch  = rem & 15;
            const __nv_bfloat16* src = (hf ? klp : khp) + (size_t)(key0 + row) * HDP_ + ch * 8;
            cpasync16(kb + hf * FKS + row * 136 + ch * 8, src);
        }
        #pragma unroll
        for (int i = 0; i < 8; i++) {
            int idx = tid + i * 256;
            int hf  = idx >> 10;
            int rem = idx & 1023;
            int row = rem >> 3;
            int ch  = rem & 7;
            const __nv_bfloat16* src = (hf ? vlp : vhp) + (size_t)row * NN_ + key0 + ch * 8;
            cpasync16(vb + hf * FVS + row * 72 + ch * 8, src);
        }
    };

    kvload(0, 0);
    CP_COMMIT();

    float m0 = -1e30f, m1 = -1e30f, l0 = 0.f, l1 = 0.f;
    float acco[16][4];
    #pragma unroll
    for (int i = 0; i < 16; i++)
        #pragma unroll
        for (int q = 0; q < 4; q++) acco[i][q] = 0.f;

    const int arow = wid * 16 + g;

    for (int j = 0; j < NKT; ++j) {
        if (j + 1 < NKT) {
            kvload(j + 1, (j + 1) & 1);
            CP_COMMIT();
            CP_WAIT(1);
        } else {
            CP_WAIT(0);
        }
        __syncthreads();

        const __nv_bfloat16* kbh = sKb + (j & 1) * 2 * FKS;
        const __nv_bfloat16* kbl = kbh + FKS;
        const __nv_bfloat16* vbh = sVb + (j & 1) * 2 * FVS;
        const __nv_bfloat16* vbl = vbh + FVS;

        float accs[8][4];
        #pragma unroll
        for (int i = 0; i < 8; i++)
            #pragma unroll
            for (int q = 0; q < 4; q++) accs[i][q] = 0.f;

        // ---- S = Q @ K^T via ldmatrix ----
        #pragma unroll
        for (int ks = 0; ks < 8; ++ks) {
            uint32_t ahh[4], alo[4];
            ldmA(ahh, sQh + (wid * 16) * 136 + ks * 16, 136);
            ldmA(alo, sQl + (wid * 16) * 136 + ks * 16, 136);
            #pragma unroll
            for (int ntp = 0; ntp < 4; ++ntp) {
                uint32_t bh4[4], bl4[4];
                ldmB(bh4, kbh + (ntp * 16) * 136 + ks * 16, 136);
                ldmB(bl4, kbl + (ntp * 16) * 136 + ks * 16, 136);
                #pragma unroll
                for (int half = 0; half < 2; ++half) {
                    uint32_t bh[2] = {bh4[half * 2], bh4[half * 2 + 1]};
                    uint32_t bl[2] = {bl4[half * 2], bl4[half * 2 + 1]};
                    int nt = ntp * 2 + half;
                    MMA_BF16(accs[nt], ahh, bh);
                    MMA_BF16(accs[nt], ahh, bl);
                    MMA_BF16(accs[nt], alo, bh);
                }
            }
        }

        // ---- online softmax ----
        float t0 = -1e30f, t1 = -1e30f;
        #pragma unroll
        for (int nt = 0; nt < 8; ++nt) {
            t0 = fmaxf(t0, fmaxf(accs[nt][0], accs[nt][1]));
            t1 = fmaxf(t1, fmaxf(accs[nt][2], accs[nt][3]));
        }
        t0 = fmaxf(t0, __shfl_xor_sync(0xffffffffu, t0, 1));
        t0 = fmaxf(t0, __shfl_xor_sync(0xffffffffu, t0, 2));
        t1 = fmaxf(t1, __shfl_xor_sync(0xffffffffu, t1, 1));
        t1 = fmaxf(t1, __shfl_xor_sync(0xffffffffu, t1, 2));
        float nm0 = fmaxf(m0, t0), nm1 = fmaxf(m1, t1);
        float sc0 = __expf(m0 - nm0), sc1 = __expf(m1 - nm1);

        uint32_t ph[4][4], pl[4][4];
        float ps0 = 0.f, ps1 = 0.f;
        #pragma unroll
        for (int kk = 0; kk < 4; ++kk) {
            float p00 = __expf(accs[2 * kk][0] - nm0);
            float p01 = __expf(accs[2 * kk][1] - nm0);
            float p02 = __expf(accs[2 * kk][2] - nm1);
            float p03 = __expf(accs[2 * kk][3] - nm1);
            float p10 = __expf(accs[2 * kk + 1][0] - nm0);
            float p11 = __expf(accs[2 * kk + 1][1] - nm0);
            float p12 = __expf(accs[2 * kk + 1][2] - nm1);
            float p13 = __expf(accs[2 * kk + 1][3] - nm1);
            ps0 += p00 + p01 + p10 + p11;
            ps1 += p02 + p03 + p12 + p13;
            split2(p00, p01, ph[kk][0], pl[kk][0]);
            split2(p02, p03, ph[kk][1], pl[kk][1]);
            split2(p10, p11, ph[kk][2], pl[kk][2]);
            split2(p12, p13, ph[kk][3], pl[kk][3]);
        }
        ps0 += __shfl_xor_sync(0xffffffffu, ps0, 1);
        ps0 += __shfl_xor_sync(0xffffffffu, ps0, 2);
        ps1 += __shfl_xor_sync(0xffffffffu, ps1, 1);
        ps1 += __shfl_xor_sync(0xffffffffu, ps1, 2);
        l0 = l0 * sc0 + ps0;
        l1 = l1 * sc1 + ps1;
        m0 = nm0;
        m1 = nm1;

        #pragma unroll
        for (int nt = 0; nt < 16; ++nt) {
            acco[nt][0] *= sc0; acco[nt][1] *= sc0;
            acco[nt][2] *= sc1; acco[nt][3] *= sc1;
        }

        // ---- O += P @ V via ldmatrix ----
        #pragma unroll
        for (int ntp = 0; ntp < 8; ++ntp) {
            #pragma unroll
            for (int kk = 0; kk < 4; ++kk) {
                uint32_t bh4[4], bl4[4];
                ldmB(bh4, vbh + (ntp * 16) * 72 + kk * 16, 72);
                ldmB(bl4, vbl + (ntp * 16) * 72 + kk * 16, 72);
                #pragma unroll
                for (int half = 0; half < 2; ++half) {
                    uint32_t bh[2] = {bh4[half * 2], bh4[half * 2 + 1]};
                    uint32_t bl[2] = {bl4[half * 2], bl4[half * 2 + 1]};
                    int nt = ntp * 2 + half;
                    MMA_BF16(acco[nt], ph[kk], bh);
                    MMA_BF16(acco[nt], ph[kk], bl);
                    MMA_BF16(acco[nt], pl[kk], bh);
                }
            }
        }
        __syncthreads();
    }

    float i0 = 1.0f / l0, i1 = 1.0f / l1;
    int r0 = bm + arow;
    #pragma unroll
    for (int nt = 0; nt < 16; ++nt) {
        int col = nt * 8 + c * 2;
        if (col < HD_) {
            attno[(size_t)r0 * HH_ + h * HD_ + col]       = acco[nt][0] * i0;
            attno[(size_t)(r0 + 8) * HH_ + h * HD_ + col] = acco[nt][2] * i1;
        }
        if (col + 1 < HD_) {
            attno[(size_t)r0 * HH_ + h * HD_ + col + 1]       = acco[nt][1] * i0;
            attno[(size_t)(r0 + 8) * HH_ + h * HD_ + col + 1] = acco[nt][3] * i1;
        }
    }
}

// ---------------- unified bf16-split tensor-core GEMM (NT) --------------------
__global__ __launch_bounds__(256, 1)
void gemm_mma_v2(const void* __restrict__ A_, const void* __restrict__ Alo_,
                 const float* __restrict__ A2f, int lda,
                 const __nv_bfloat16* __restrict__ B1h, const __nv_bfloat16* __restrict__ B1l,
                 const __nv_bfloat16* __restrict__ B2h, const __nv_bfloat16* __restrict__ B2l,
                 int ldb,
                 const float* __restrict__ bias,
                 float* __restrict__ C, int ldc,
                 int Nfull, int Kpad, int kValidA, float alpha,
                 int afp32, int relu, int mode,
                 size_t zsA, size_t zsB, size_t zsC, int ksplit) {
    __shared__ __align__(16) __nv_bfloat16 sAh[128 * 40];
    __shared__ __align__(16) __nv_bfloat16 sAl[128 * 40];
    __shared__ __align__(16) __nv_bfloat16 sBh[128 * 40];
    __shared__ __align__(16) __nv_bfloat16 sBl[128 * 40];

    const int tid  = threadIdx.x;
    const int lane = tid & 31;
    const int wid  = tid >> 5;
    const int wm   = wid & 3;
    const int wn   = wid >> 2;
    const int bm   = blockIdx.y * 128;
    const int bn   = blockIdx.x * 128;
    const int z    = blockIdx.z;
    const int h    = z / ksplit;
    const int ks   = z - h * ksplit;
    const int klen = Kpad / ksplit;
    const int kb   = ks * klen;
    const int kValid = kValidA - kb;

    float acc[2][8][4];
    #pragma unroll
    for (int i = 0; i < 2; i++)
        #pragma unroll
        for (int j = 0; j < 8; j++)
            #pragma unroll
            for (int q = 0; q < 4; q++) acc[i][j][q] = 0.f;

    const int npairs = (afp32 && A2f != nullptr) ? 2 : 1;

    for (int pr = 0; pr < npairs; ++pr) {
        const float* Af = nullptr;
        const __nv_bfloat16* Ahi = nullptr;
        const __nv_bfloat16* Alo = nullptr;
        if (afp32) {
            Af = (pr ? A2f : (const float*)A_) + h * zsA + kb;
        } else {
            Ahi = (const __nv_bfloat16*)A_  + h * zsA + kb;
            Alo = (const __nv_bfloat16*)Alo_ + h * zsA + kb;
        }
        const __nv_bfloat16* Bh = (pr ? B2h : B1h) + h * zsB + kb;
        const __nv_bfloat16* Bl = (pr ? B2l : B1l) + h * zsB + kb;

        uint4 stA[4], stB[4];

        auto prefetch = [&](int k0) {
            if (afp32) {
                #pragma unroll
                for (int i = 0; i < 4; i++) {
                    int l = tid + i * 256;
                    int r = l >> 3, g4 = l & 7;
                    float4 v = make_float4(0.f, 0.f, 0.f, 0.f);
                    if (k0 + g4 * 4 < kValid)
                        v = *(const float4*)(Af + (size_t)(bm + r) * lda + k0 + g4 * 4);
                    stA[i] = *(uint4*)&v;
                }
            } else {
                #pragma unroll
                for (int i = 0; i < 2; i++) {
                    int l = tid + i * 256;
                    int r = l >> 2, g = l & 3;
                    stA[i]     = *(const uint4*)(Ahi + (size_t)(bm + r) * lda + k0 + g * 8);
                    stA[i + 2] = *(const uint4*)(Alo + (size_t)(bm + r) * lda + k0 + g * 8);
                }
            }
            #pragma unroll
            for (int i = 0; i < 2; i++) {
                int l = tid + i * 256;
                int r = l >> 2, g = l & 3;
                if (bn + r < Nfull) {
                    stB[i]     = *(const uint4*)(Bh + (size_t)(bn + r) * ldb + k0 + g * 8);
                    stB[i + 2] = *(const uint4*)(Bl + (size_t)(bn + r) * ldb + k0 + g * 8);
                } else {
                    stB[i] = make_uint4(0, 0, 0, 0);
                    stB[i + 2] = make_uint4(0, 0, 0, 0);
                }
            }
        };

        auto store_smem = [&]() {
            if (afp32) {
                #pragma unroll
                for (int i = 0; i < 4; i++) {
                    int l = tid + i * 256;
                    int r = l >> 3, g4 = l & 7;
                    float4 v = *(float4*)&stA[i];
                    __nv_bfloat16 h0, l0, h1, l1, h2, l2, h3, l3;
                    splitf(v.x, h0, l0); splitf(v.y, h1, l1);
                    splitf(v.z, h2, l2); splitf(v.w, h3, l3);
                    __nv_bfloat162* pph = (__nv_bfloat162*)(sAh + r * 40 + g4 * 4);
                    __nv_bfloat162* ppl = (__nv_bfloat162*)(sAl + r * 40 + g4 * 4);
                    __nv_bfloat162 t2;
                    t2.x = h0; t2.y = h1; pph[0] = t2;
                    t2.x = h2; t2.y = h3; pph[1] = t2;
                    t2.x = l0; t2.y = l1; ppl[0] = t2;
                    t2.x = l2; t2.y = l3; ppl[1] = t2;
                }
            } else {
                #pragma unroll
                for (int i = 0; i < 2; i++) {
                    int l = tid + i * 256;
                    int r = l >> 2, g = l & 3;
                    *(uint4*)(sAh + r * 40 + g * 8) = stA[i];
                    *(uint4*)(sAl + r * 40 + g * 8) = stA[i + 2];
                }
            }
            #pragma unroll
            for (int i = 0; i < 2; i++) {
                int l = tid + i * 256;
                int r = l >> 2, g = l & 3;
                *(uint4*)(sBh + r * 40 + g * 8) = stB[i];
                *(uint4*)(sBl + r * 40 + g * 8) = stB[i + 2];
            }
        };

        prefetch(0);
        for (int k0 = 0; k0 < klen; k0 += 32) {
            store_smem();
            __syncthreads();
            if (k0 + 32 < klen) prefetch(k0 + 32);

            #pragma unroll
            for (int ksf = 0; ksf < 2; ++ksf) {
                uint32_t ah[2][4], al[2][4];
                #pragma unroll
                for (int mt = 0; mt < 2; ++mt) {
                    ldmA(ah[mt], sAh + (wm * 32 + mt * 16) * 40 + ksf * 16, 40);
                    ldmA(al[mt], sAl + (wm * 32 + mt * 16) * 40 + ksf * 16, 40);
                }
                #pragma unroll
                for (int ntp = 0; ntp < 4; ++ntp) {
                    uint32_t bh4[4], bl4[4];
                    ldmB(bh4, sBh + (wn * 64 + ntp * 16) * 40 + ksf * 16, 40);
                    ldmB(bl4, sBl + (wn * 64 + ntp * 16) * 40 + ksf * 16, 40);
                    #pragma unroll
                    for (int half = 0; half < 2; ++half) {
                        uint32_t bh[2] = {bh4[half * 2], bh4[half * 2 + 1]};
                        uint32_t bl[2] = {bl4[half * 2], bl4[half * 2 + 1]};
                        int nt = ntp * 2 + half;
                        #pragma unroll
                        for (int mt = 0; mt < 2; ++mt) {
                            MMA_BF16(acc[mt][nt], ah[mt], bh);
                            MMA_BF16(acc[mt][nt], ah[mt], bl);
                            MMA_BF16(acc[mt][nt], al[mt], bh);
                        }
                    }
                }
            }
            __syncthreads();
        }
    }

    float* Cp = C + h * zsC;
    if (mode == 0) {
        #pragma unroll
        for (int mt = 0; mt < 2; ++mt) {
            int row = bm + wm * 32 + mt * 16 + (lane >> 2);
            #pragma unroll
            for (int nt = 0; nt < 8; ++nt) {
                int gc = bn + wn * 64 + nt * 8 + ((lane & 3) << 1);
                #pragma unroll
                for (int j = 0; j < 2; ++j) {
                    if (gc + j < Nfull) {
                        float bsv = bias ? bias[gc + j] : 0.f;
                        float v0 = alpha * acc[mt][nt][j] + bsv;
                        float v1 = alpha * acc[mt][nt][j + 2] + bsv;
                        if (relu) { v0 = fmaxf(v0, 0.f); v1 = fmaxf(v1, 0.f); }
                        Cp[(size_t)row * ldc + gc + j] = v0;
                        Cp[(size_t)(row + 8) * ldc + gc + j] = v1;
                    }
                }
            }
        }
    } else {
        int hofs = h * HD_;
        #pragma unroll
        for (int mt = 0; mt < 2; ++mt) {
            int row = bm + wm * 32 + mt * 16 + (lane >> 2);
            #pragma unroll
            for (int nt = 0; nt < 8; ++nt) {
                int gc = wn * 64 + nt * 8 + ((lane & 3) << 1);
                #pragma unroll
                for (int j = 0; j < 2; ++j) {
                    if (gc + j < Nfull) {
                        atomicAdd(&C[(size_t)row * ldc + hofs + gc + j], acc[mt][nt][j]);
                        atomicAdd(&C[(size_t)(row + 8) * ldc + hofs + gc + j], acc[mt][nt][j + 2]);
                    }
                }
            }
        }
    }
}

// ---------------- launch -----------------------------------------------------
extern "C" void kernel_launch(void* const* d_in, const int* in_sizes, int n_in,
                              void* d_out, int out_size) {
    const float* x        = (const float*)d_in[0];
    const int*   ei       = (const int*)d_in[1];
    const float* W1_self  = (const float*)d_in[2];
    const float* W1_neigh = (const float*)d_in[3];
    const float* b1       = (const float*)d_in[4];
    const float* W_in     = (const float*)d_in[5];
    const float* b_in     = (const float*)d_in[6];
    const float* W_out    = (const float*)d_in[7];
    const float* b_out    = (const float*)d_in[8];
    const float* W2_self  = (const float*)d_in[9];
    const float* W2_neigh = (const float*)d_in[10];
    const float* b2       = (const float*)d_in[11];
    const float* Wc       = (const float*)d_in[12];
    const float* bc       = (const float*)d_in[13];

    float* out_x      = (float*)d_out;
    float* out_logits = (float*)d_out + (size_t)NN_ * OUT_;

    int* degi;
    float *mean, *h1, *qkv, *attno, *h2, *tmp2;
    cudaGetSymbolAddress((void**)&degi,  g_degi);
    cudaGetSymbolAddress((void**)&mean,  g_mean);
    cudaGetSymbolAddress((void**)&h1,    g_h1);
    cudaGetSymbolAddress((void**)&qkv,   g_qkv);
    cudaGetSymbolAddress((void**)&attno, g_attno);
    cudaGetSymbolAddress((void**)&h2,    g_h2);
    cudaGetSymbolAddress((void**)&tmp2,  g_tmp2);

    __nv_bfloat16 *qh, *ql, *kh, *kl, *vth, *vtl;
    __nv_bfloat16 *w1sh, *w1sl, *w1nh, *w1nl, *winh, *winl, *woh, *wol;
    __nv_bfloat16 *w2sh, *w2sl, *w2nh, *w2nl, *wch, *wcl;
    cudaGetSymbolAddress((void**)&qh,   g_qh);
    cudaGetSymbolAddress((void**)&ql,   g_ql);
    cudaGetSymbolAddress((void**)&kh,   g_kh);
    cudaGetSymbolAddress((void**)&kl,   g_kl);
    cudaGetSymbolAddress((void**)&vth,  g_vth);
    cudaGetSymbolAddress((void**)&vtl,  g_vtl);
    cudaGetSymbolAddress((void**)&w1sh, g_w1sh); cudaGetSymbolAddress((void**)&w1sl, g_w1sl);
    cudaGetSymbolAddress((void**)&w1nh, g_w1nh); cudaGetSymbolAddress((void**)&w1nl, g_w1nl);
    cudaGetSymbolAddress((void**)&winh, g_winh); cudaGetSymbolAddress((void**)&winl, g_winl);
    cudaGetSymbolAddress((void**)&woh,  g_woh);  cudaGetSymbolAddress((void**)&wol,  g_wol);
    cudaGetSymbolAddress((void**)&w2sh, g_w2sh); cudaGetSymbolAddress((void**)&w2sl, g_w2sl);
    cudaGetSymbolAddress((void**)&w2nh, g_w2nh); cudaGetSymbolAddress((void**)&w2nl, g_w2nl);
    cudaGetSymbolAddress((void**)&wch,  g_wch);  cudaGetSymbolAddress((void**)&wcl,  g_wcl);

    cudaFuncSetAttribute(flash_attn, cudaFuncAttributeMaxDynamicSharedMemorySize, FLASH_SMEM);

    const float scale = 1.0f / sqrtf((float)HD_);

    // ---- CSR build ----
    zero_i<<<16, 256>>>(degi, NN_);
    count_deg<<<EE_ / 256, 256>>>(ei);
    scan_offsets<<<1, 1024>>>();
    csr_fill<<<EE_ / 256, 256>>>(ei);

    // ---- weight pre-splits ----
    split_w<<<(HH_ * KP500 + 255) / 256, 256>>>(W1_self, HH_, IN_, KP500, w1sh, w1sl);
    split_w<<<(HH_ * KP500 + 255) / 256, 256>>>(W1_neigh, HH_, IN_, KP500, w1nh, w1nl);
    split_w<<<(3 * HH_ * KP500 + 255) / 256, 256>>>(W_in, 3 * HH_, HH_, KP500, winh, winl);
    split_w<<<(HH_ * KP500 + 255) / 256, 256>>>(W_out, HH_, HH_, KP500, woh, wol);
    split_w<<<(OUT_ * KP500 + 255) / 256, 256>>>(W2_self, OUT_, HH_, KP500, w2sh, w2sl);
    split_w<<<(OUT_ * KP500 + 255) / 256, 256>>>(W2_neigh, OUT_, HH_, KP500, w2nh, w2nl);
    split_w<<<(int)(((size_t)CC_ * 128 + 255) / 256), 256>>>(Wc, CC_, OUT_, 128, wch, wcl);

    // ---- SAGE 1 ----
    gather_mean<<<NN_, 128>>>(x, mean, IN_ / 4);
    {
        dim3 grid(4, 32, 1);
        gemm_mma_v2<<<grid, 256>>>(x, nullptr, mean, IN_,
                                   w1sh, w1sl, w1nh, w1nl, KP500,
                                   b1, h1, HH_,
                                   HH_, KP500, IN_, 1.0f, 1, 1, 0,
                                   0, 0, 0, 1);
    }

    // ---- qkv projection ----
    {
        dim3 grid(12, 32, 1);
        gemm_mma_v2<<<grid, 256>>>(h1, nullptr, nullptr, HH_,
                                   winh, winl, nullptr, nullptr, KP500,
                                   b_in, qkv, 3 * HH_,
                                   3 * HH_, KP500, HH_, 1.0f, 1, 0, 0,
                                   0, 0, 0, 1);
    }
    convert_qk_kernel<<<(NHEAD * NN_ * HDP_ + 255) / 256, 256>>>(qkv, scale);
    convert_v_kernel<<<(NHEAD * HDP_ * NN_ + 255) / 256, 256>>>(qkv);

    // ---- fused flash attention ----
    {
        dim3 grid(NN_ / 128, NHEAD);
        flash_attn<<<grid, 256, FLASH_SMEM>>>(qh, ql, kh, kl, vth, vtl, attno);
    }

    // ---- out projection ----
    {
        dim3 grid(4, 32, 1);
        gemm_mma_v2<<<grid, 256>>>(attno, nullptr, nullptr, HH_,
                                   woh, wol, nullptr, nullptr, KP500,
                                   b_out, h2, HH_,
                                   HH_, KP500, HH_, 1.0f, 1, 1, 0,
                                   0, 0, 0, 1);
    }

    // ---- SAGE 2 (split-K=4 atomic, then bias+relu) ----
    gather_mean<<<NN_, 128>>>(h2, mean, HH_ / 4);
    zero_f<<<1600, 256>>>(tmp2, NN_ * OUT_);
    {
        dim3 grid(1, 32, 4);
        gemm_mma_v2<<<grid, 256>>>(h2, nullptr, mean, HH_,
                                   w2sh, w2sl, w2nh, w2nl, KP500,
                                   nullptr, tmp2, OUT_,
                                   OUT_, KP500, HH_, 1.0f, 1, 0, 1,
                                   0, 0, 0, 4);
    }
    bias_relu_kernel<<<(NN_ * OUT_ + 255) / 256, 256>>>(tmp2, b2, out_x, NN_ * OUT_, OUT_);

    // ---- classifier ----
    {
        dim3 grid(CCP_ / 128, 32, 1);
        gemm_mma_v2<<<grid, 256>>>(out_x, nullptr, nullptr, OUT_,
                                   wch, wcl, nullptr, nullptr, 128,
                                   bc, out_logits, CC_,
                                   CC_, 128, OUT_, 1.0f, 1, 0, 0,
                                   0, 0, 0, 1);
    }
}